// round 13
// baseline (speedup 1.0000x reference)
#include <cuda_runtime.h>
#include <math.h>

#define B 4
#define H 16
#define T 8192
#define D 64
#define C 64
#define W 128
#define NC 64
#define BH (B*H)

// ---------------- scratch ----------------
__device__ float g_knorm[(size_t)B*H*T*D];
__device__ float g_dists[(size_t)B*H*C*T];
__device__ unsigned char g_bucketsB[B*H*T];
__device__ float g_part[(size_t)B*H*C*D];
__device__ int   g_bins[H*C];
__device__ float g_meansu[H*C*D];
__device__ int   g_indices[B*H*T];
__device__ int   g_count[B*H*T];

// Correctly-rounded division via Markstein sequence (r = __frcp_rn(n)).
__device__ __forceinline__ float fdiv_rn_m(float x, float n, float r) {
    float q = __fmul_rn(x, r);
    float e = __fmaf_rn(-q, n, x);
    return __fmaf_rn(e, r, q);
}

// packed f32x2 helpers (sm_103a native). Per-component IEEE rn fma —
// each component's chain is bit-identical to the scalar chain.
__device__ __forceinline__ unsigned long long pk2(float a, float b) {
    unsigned long long r; asm("mov.b64 %0,{%1,%2};" : "=l"(r) : "f"(a), "f"(b)); return r;
}
__device__ __forceinline__ void upk2(unsigned long long u, float& a, float& b) {
    asm("mov.b64 {%0,%1},%2;" : "=f"(a), "=f"(b) : "l"(u));
}
__device__ __forceinline__ unsigned long long fmaf2(unsigned long long a, unsigned long long b, unsigned long long c) {
    unsigned long long d; asm("fma.rn.f32x2 %0,%1,%2,%3;" : "=l"(d) : "l"(a), "l"(b), "l"(c)); return d;
}

// ---------------- K0: zero accumulators ----------------
__global__ void k_zero(float* __restrict__ out) {
    size_t i = (size_t)blockIdx.x * blockDim.x + threadIdx.x;
    size_t stride = (size_t)gridDim.x * blockDim.x;
    const size_t NOUT = (size_t)B*H*T*D;
    for (size_t p = i; p < NOUT; p += stride) out[p] = 0.f;
    for (size_t p = i; p < (size_t)B*H*T; p += stride) g_count[p] = 0;
    for (size_t p = i; p < (size_t)H*C; p += stride) g_bins[p] = 0;
}

// ---------------- K1: k_norm (bit-exact: sequential fused fma ssq; Markstein div) ----------------
__global__ void k_norm(const float* __restrict__ qk) {
    int tok = blockIdx.x * blockDim.x + threadIdx.x;
    if (tok >= B*H*T) return;
    const float4* src = (const float4*)(qk + (size_t)tok * D);
    float v[64];
    #pragma unroll
    for (int i = 0; i < 16; i++) {
        float4 q = src[i];
        v[4*i+0] = q.x; v[4*i+1] = q.y; v[4*i+2] = q.z; v[4*i+3] = q.w;
    }
    float s = 0.f;
    #pragma unroll
    for (int d = 0; d < 64; d++) s = __fmaf_rn(v[d], v[d], s);
    float n = fmaxf(__fsqrt_rn(s), 1e-12f);
    float r = __frcp_rn(n);
    float4* dst = (float4*)(g_knorm + (size_t)tok * D);
    #pragma unroll
    for (int i = 0; i < 16; i++) {
        float4 o;
        o.x = fdiv_rn_m(v[4*i+0], n, r);
        o.y = fdiv_rn_m(v[4*i+1], n, r);
        o.z = fdiv_rn_m(v[4*i+2], n, r);
        o.w = fdiv_rn_m(v[4*i+3], n, r);
        dst[i] = o;
    }
}

// ---------------- K2: buckets = argmax_c (k_norm . means), FFMA2 packed ----------------
// sM[d][c] (pitch 64), sT2[d][2r] token values DUPLICATED so (q,q) splats load
// directly as halves of an LDS.128. Outputs packed over adjacent c (independent
// accumulators); each component chain = sequential ascending-d fma (bit-exact).
__global__ void k_buckets(const float* __restrict__ means) {
    __shared__ float sM[64*64];     // 16 KB [d][c]
    __shared__ float sT2[64*128];   // 32 KB [d][2r] duplicated
    int blk = blockIdx.x;
    int bh = blk / (T/64);
    int chunk = blk % (T/64);
    int h = bh % H;
    int tid = threadIdx.x;

    for (int i = tid; i < C*D; i += 256) {
        int c = i >> 6, d = i & 63;
        sM[d*64 + c] = means[(size_t)h*C*D + i];
    }
    size_t base = ((size_t)bh*T + (size_t)chunk*64) * D;
    for (int i = tid; i < 64*D; i += 256) {
        int r = i >> 6, d = i & 63;
        float val = g_knorm[base + i];
        *(float2*)&sT2[d*128 + 2*r] = make_float2(val, val);
    }
    __syncthreads();

    int tx = tid & 15, ty = tid >> 4;
    int tok0 = ty*4, c0 = tx*4;
    unsigned long long a2[4][2];
    #pragma unroll
    for (int r = 0; r < 4; r++) { a2[r][0] = 0ull; a2[r][1] = 0ull; }

    #pragma unroll 8
    for (int d = 0; d < 64; d++) {
        float4 qa = *(const float4*)&sT2[d*128 + 2*tok0];       // q0 q0 q1 q1
        float4 qb = *(const float4*)&sT2[d*128 + 2*tok0 + 4];   // q2 q2 q3 q3
        float4 m  = *(const float4*)&sM[d*64 + c0];
        unsigned long long m01 = pk2(m.x, m.y), m23 = pk2(m.z, m.w);
        unsigned long long q0 = pk2(qa.x, qa.y), q1 = pk2(qa.z, qa.w);
        unsigned long long q2 = pk2(qb.x, qb.y), q3 = pk2(qb.z, qb.w);
        a2[0][0] = fmaf2(q0, m01, a2[0][0]); a2[0][1] = fmaf2(q0, m23, a2[0][1]);
        a2[1][0] = fmaf2(q1, m01, a2[1][0]); a2[1][1] = fmaf2(q1, m23, a2[1][1]);
        a2[2][0] = fmaf2(q2, m01, a2[2][0]); a2[2][1] = fmaf2(q2, m23, a2[2][1]);
        a2[3][0] = fmaf2(q3, m01, a2[3][0]); a2[3][1] = fmaf2(q3, m23, a2[3][1]);
    }
    __syncthreads();

    float* sSim = sT2;   // staging [tok][c] pitch 65 (4160 floats <= 8192)
    #pragma unroll
    for (int r = 0; r < 4; r++) {
        float f0, f1, f2, f3;
        upk2(a2[r][0], f0, f1);
        upk2(a2[r][1], f2, f3);
        float* row = &sSim[(tok0 + r)*65 + c0];
        row[0] = f0; row[1] = f1; row[2] = f2; row[3] = f3;
    }
    __syncthreads();

    if (tid < 64) {
        float best = -1e30f; int bi = 0;
        #pragma unroll 8
        for (int c = 0; c < C; c++) {
            float s = sSim[tid*65 + c];
            if (s > best) { best = s; bi = c; }   // strict > : first index on ties
        }
        g_bucketsB[(size_t)bh*T + chunk*64 + tid] = (unsigned char)bi;
    }
}

// ---------------- K3: cluster sums — byte buckets, vcmpeq4 scan (t-ascending chains) ----------------
__global__ __launch_bounds__(1024, 1) void k_sumsC() {
    __shared__ unsigned int sb[T/4];      // 8 KB
    int bh = blockIdx.x >> 1;
    int half = blockIdx.x & 1;
    int tid = threadIdx.x;
    int lane = tid & 31, wid = tid >> 5;
    size_t base = (size_t)bh * T;
    for (int i = tid; i < T/16; i += 1024)
        ((uint4*)sb)[i] = ((const uint4*)(g_bucketsB + base))[i];
    __syncthreads();

    int c = half*32 + wid;
    unsigned int cc = (unsigned int)c * 0x01010101u;
    float ax = 0.f, ay = 0.f;
    int cnt = 0;

    #define ADDTOK(tt) { float2 xv = ((const float2*)(g_knorm + (base + (tt))*D))[lane]; \
                         ax = __fadd_rn(ax, xv.x); ay = __fadd_rn(ay, xv.y); cnt++; }
    #define SCANW(u, t0) { unsigned int m = __vcmpeq4((u), cc); \
        if (m) { if (m & 0x000000FFu) ADDTOK((t0)+0); if (m & 0x0000FF00u) ADDTOK((t0)+1); \
                 if (m & 0x00FF0000u) ADDTOK((t0)+2); if (m & 0xFF000000u) ADDTOK((t0)+3); } }

    for (int t = 0; t < T; t += 16) {
        uint4 w = *(const uint4*)&sb[t >> 2];
        SCANW(w.x, t+0);
        SCANW(w.y, t+4);
        SCANW(w.z, t+8);
        SCANW(w.w, t+12);
    }
    #undef SCANW
    #undef ADDTOK

    float2 o; o.x = ax; o.y = ay;
    ((float2*)(g_part + ((size_t)bh*C + c) * D))[lane] = o;
    if (lane == 0) atomicAdd(&g_bins[(bh & (H-1))*C + c], cnt);
}

// ---------------- K4: means_upd (b-ascending combine + fused ssq + Markstein div) ----------------
__global__ void k_meansupd(const float* __restrict__ means) {
    int inst = blockIdx.x * blockDim.x + threadIdx.x;
    if (inst >= H*C) return;
    float sv[64];
    #pragma unroll 4
    for (int d = 0; d < D; d++) {
        float s = g_part[((size_t)0*1024 + inst)*D + d];
        s = __fadd_rn(s, g_part[((size_t)1*1024 + inst)*D + d]);
        s = __fadd_rn(s, g_part[((size_t)2*1024 + inst)*D + d]);
        s = __fadd_rn(s, g_part[((size_t)3*1024 + inst)*D + d]);
        sv[d] = s;
    }
    float ssq = 0.f;
    #pragma unroll
    for (int d = 0; d < D; d++) ssq = __fmaf_rn(sv[d], sv[d], ssq);
    float n = fmaxf(__fsqrt_rn(ssq), 1e-12f);
    float r = __frcp_rn(n);
    bool empty = (g_bins[inst] == 0);
    #pragma unroll 4
    for (int d = 0; d < D; d++) {
        float o = empty ? means[(size_t)inst*D + d] : fdiv_rn_m(sv[d], n, r);
        g_meansu[(size_t)inst*D + d] = o;
    }
}

// ---------------- K5: dists, FFMA2 packed (bit-exact per component) ----------------
__global__ void k_dists() {
    __shared__ float sM[64*64];
    __shared__ float sT2[64*128];
    int blk = blockIdx.x;
    int bh = blk / (T/64);
    int chunk = blk % (T/64);
    int h = bh % H;
    int tid = threadIdx.x;

    for (int i = tid; i < C*D; i += 256) {
        int c = i >> 6, d = i & 63;
        sM[d*64 + c] = g_meansu[(size_t)h*C*D + i];
    }
    size_t base = ((size_t)bh*T + (size_t)chunk*64) * D;
    for (int i = tid; i < 64*D; i += 256) {
        int r = i >> 6, d = i & 63;
        float val = g_knorm[base + i];
        *(float2*)&sT2[d*128 + 2*r] = make_float2(val, val);
    }
    __syncthreads();

    int tx = tid & 15, ty = tid >> 4;
    int tok0 = ty*4, c0 = tx*4;
    unsigned long long a2[4][2];
    #pragma unroll
    for (int r = 0; r < 4; r++) { a2[r][0] = 0ull; a2[r][1] = 0ull; }

    #pragma unroll 8
    for (int d = 0; d < 64; d++) {
        float4 qa = *(const float4*)&sT2[d*128 + 2*tok0];
        float4 qb = *(const float4*)&sT2[d*128 + 2*tok0 + 4];
        float4 m  = *(const float4*)&sM[d*64 + c0];
        unsigned long long m01 = pk2(m.x, m.y), m23 = pk2(m.z, m.w);
        unsigned long long q0 = pk2(qa.x, qa.y), q1 = pk2(qa.z, qa.w);
        unsigned long long q2 = pk2(qb.x, qb.y), q3 = pk2(qb.z, qb.w);
        a2[0][0] = fmaf2(q0, m01, a2[0][0]); a2[0][1] = fmaf2(q0, m23, a2[0][1]);
        a2[1][0] = fmaf2(q1, m01, a2[1][0]); a2[1][1] = fmaf2(q1, m23, a2[1][1]);
        a2[2][0] = fmaf2(q2, m01, a2[2][0]); a2[2][1] = fmaf2(q2, m23, a2[2][1]);
        a2[3][0] = fmaf2(q3, m01, a2[3][0]); a2[3][1] = fmaf2(q3, m23, a2[3][1]);
    }
    __syncthreads();

    float* sSim = sT2;   // staging [c][tok] pitch 65
    #pragma unroll
    for (int r = 0; r < 4; r++) {
        float f0, f1, f2, f3;
        upk2(a2[r][0], f0, f1);
        upk2(a2[r][1], f2, f3);
        sSim[(c0+0)*65 + tok0 + r] = f0;
        sSim[(c0+1)*65 + tok0 + r] = f1;
        sSim[(c0+2)*65 + tok0 + r] = f2;
        sSim[(c0+3)*65 + tok0 + r] = f3;
    }
    __syncthreads();

    for (int i = tid; i < C*64; i += 256) {
        int c = i >> 6, t = i & 63;
        g_dists[((size_t)bh*C + c)*T + (size_t)chunk*64 + t] = sSim[c*65 + t];
    }
}

// ---------------- K6: top-128 per (b,h,c): radix select + bitonic index sort ----------------
__global__ void k_topk() {
    __shared__ unsigned int keys[T];
    __shared__ unsigned int hist[256];
    __shared__ unsigned int sh_pref;
    __shared__ int sh_k;
    __shared__ int outbuf[W];
    __shared__ int gtc;
    __shared__ int eqbase;
    __shared__ int warpTot[8];

    int inst = blockIdx.x;
    int bh = inst / C;
    int c = inst % C;
    int tid = threadIdx.x, lane = tid & 31, wid = tid >> 5;

    const float* row = g_dists + (size_t)inst * T;
    for (int i = tid; i < T; i += 256) {
        unsigned int u = __float_as_uint(row[i]);
        keys[i] = (u & 0x80000000u) ? ~u : (u | 0x80000000u);
    }
    __syncthreads();

    unsigned int prefix = 0; int k = 128;
    for (int sh = 24; sh >= 0; sh -= 8) {
        hist[tid] = 0;
        __syncthreads();
        unsigned int hmask = (sh == 24) ? 0u : (0xFFFFFFFFu << (sh + 8));
        for (int i = tid; i < T; i += 256) {
            unsigned int kk = keys[i];
            if ((kk & hmask) == prefix) atomicAdd(&hist[(kk >> sh) & 255], 1u);
        }
        __syncthreads();
        if (tid == 0) {
            int cum = 0;
            for (int bkt = 255; bkt >= 0; bkt--) {
                cum += (int)hist[bkt];
                if (cum >= k) {
                    sh_pref = prefix | ((unsigned int)bkt << sh);
                    sh_k = k - (cum - (int)hist[bkt]);
                    break;
                }
            }
        }
        __syncthreads();
        prefix = sh_pref; k = sh_k;
        __syncthreads();
    }
    unsigned int Tkey = prefix;
    int k_rem = k;
    int count_gt = 128 - k_rem;

    if (tid == 0) { gtc = 0; eqbase = 0; }
    __syncthreads();

    for (int i = tid; i < T; i += 256) {
        if (keys[i] > Tkey) {
            int p = atomicAdd(&gtc, 1);
            outbuf[p] = i;
        }
    }
    __syncthreads();

    for (int ch = 0; ch < T; ch += 256) {
        int i = ch + tid;
        bool eq = (keys[i] == Tkey);
        unsigned int bal = __ballot_sync(0xffffffffu, eq);
        int wpre = __popc(bal & ((1u << lane) - 1u));
        if (lane == 0) warpTot[wid] = __popc(bal);
        __syncthreads();
        int base = eqbase;
        int woff = 0;
        for (int w = 0; w < wid; w++) woff += warpTot[w];
        if (eq) {
            int rank = base + woff + wpre;
            if (rank < k_rem) outbuf[count_gt + rank] = i;
        }
        __syncthreads();
        if (tid == 0) {
            int tot = 0;
            for (int w = 0; w < 8; w++) tot += warpTot[w];
            eqbase += tot;
        }
        __syncthreads();
        if (eqbase >= k_rem) break;
    }

    for (int size = 2; size <= 128; size <<= 1) {
        for (int stride = size >> 1; stride > 0; stride >>= 1) {
            __syncthreads();
            if (tid < 128) {
                int partner = tid ^ stride;
                if (partner > tid) {
                    bool up = ((tid & size) == 0);
                    int a = outbuf[tid], b2 = outbuf[partner];
                    if ((a > b2) == up) { outbuf[tid] = b2; outbuf[partner] = a; }
                }
            }
        }
    }
    __syncthreads();
    if (tid < 128) g_indices[(size_t)bh*T + c*W + tid] = outbuf[tid];
}

// ---------------- K7: windowed attention — rel as dense GEMM G=Q.R^T + gather ----------------
// smem: sQ[128][64], sK[128][66], sV[128][64], sR[128][66], sG[128][129], idx
#define ATTN_SMEM ((128*64 + 128*66 + 128*64 + 128*66 + 128*129) * 4 + 128 * 4)

__global__ __launch_bounds__(256, 1)
void k_attn(const float* __restrict__ qk, const float* __restrict__ v,
            const float* __restrict__ rw, float* __restrict__ out) {
    extern __shared__ float sm[];
    float* sQ = sm;                      // [128][64]
    float* sK = sQ + 128*64;             // [128][66]
    float* sV = sK + 128*66;             // [128][64]
    float* sR = sV + 128*64;             // [128][66]
    float* sG = sR + 128*66;             // [128][129]
    int*   sIdx = (int*)(sG + 128*129);

    int inst = blockIdx.x;
    int bh = inst / NC;
    int n  = inst % NC;
    int h  = bh % H;
    int tid = threadIdx.x, lane = tid & 31, wid = tid >> 5;

    if (tid < 128) sIdx[tid] = g_indices[(size_t)bh*T + n*W + tid];
    __syncthreads();

    for (int r = wid; r < 128; r += 8) {
        int g = sIdx[r];
        size_t off = ((size_t)bh*T + g) * D;
        float2 a = ((const float2*)(qk + off))[lane];
        float2 b2 = ((const float2*)(g_knorm + off))[lane];
        float2 c2 = ((const float2*)(v + off))[lane];
        sQ[r*64 + 2*lane] = a.x;  sQ[r*64 + 2*lane + 1] = a.y;
        sK[r*66 + 2*lane] = b2.x; sK[r*66 + 2*lane + 1] = b2.y;
        sV[r*64 + 2*lane] = c2.x; sV[r*64 + 2*lane + 1] = c2.y;
        float2 rr = ((const float2*)(rw + ((size_t)r*H + h)*D))[lane];
        sR[r*66 + 2*lane] = rr.x; sR[r*66 + 2*lane + 1] = rr.y;
    }
    __syncthreads();

    const float scale = 0.125f;

    // ---- Phase A: G[i][s] = Q[i] . R[s]  (dense GEMM, staged to sG) ----
    for (int p = 0; p < 4; p++) {
        #pragma unroll
        for (int q = 0; q < 4; q++) {
            int i = wid + 8*q + 32*p;
            float g[4] = {0.f, 0.f, 0.f, 0.f};
            #pragma unroll 4
            for (int d2 = 0; d2 < 32; d2++) {
                float2 qv = *(const float2*)&sQ[i*64 + 2*d2];
                #pragma unroll
                for (int jj = 0; jj < 4; jj++) {
                    float2 rv = *(const float2*)&sR[(lane + 32*jj)*66 + 2*d2];
                    g[jj] += qv.x*rv.x + qv.y*rv.y;
                }
            }
            #pragma unroll
            for (int jj = 0; jj < 4; jj++)
                sG[i*129 + lane + 32*jj] = g[jj];
        }
    }
    __syncwarp();   // each row of sG written entirely by this warp

    // ---- Phase B: S-GEMM + gather(rel) + softmax + AV + scatter ----
    for (int p = 0; p < 4; p++) {
        int irow[4];
        #pragma unroll
        for (int q = 0; q < 4; q++) irow[q] = wid + 8*q + 32*p;

        float a[4][4];
        #pragma unroll
        for (int q = 0; q < 4; q++)
            #pragma unroll
            for (int jj = 0; jj < 4; jj++) a[q][jj] = 0.f;

        #pragma unroll 4
        for (int d2 = 0; d2 < 32; d2++) {
            float2 qv[4];
            #pragma unroll
            for (int q = 0; q < 4; q++) qv[q] = *(const float2*)&sQ[irow[q]*64 + 2*d2];
            #pragma unroll
            for (int jj = 0; jj < 4; jj++) {
                float2 kv = *(const float2*)&sK[(lane + 32*jj)*66 + 2*d2];
                #pragma unroll
                for (int q = 0; q < 4; q++)
                    a[q][jj] += qv[q].x*kv.x + qv[q].y*kv.y;
            }
        }

        // rel gather: j < i  ->  += G[i][127 + j - i]
        #pragma unroll
        for (int q = 0; q < 4; q++) {
            int i = irow[q];
            #pragma unroll
            for (int jj = 0; jj < 4; jj++) {
                int j = lane + 32*jj;
                if (j < i) a[q][jj] += sG[i*129 + 127 + j - i];
            }
        }

        float pr[4][4];
        #pragma unroll
        for (int q = 0; q < 4; q++) {
            int i = irow[q];
            float m = -1e30f;
            #pragma unroll
            for (int jj = 0; jj < 4; jj++) {
                int j = lane + 32*jj;
                a[q][jj] = (j == i) ? -50000.0f : a[q][jj]*scale;
                m = fmaxf(m, a[q][jj]);
            }
            #pragma unroll
            for (int o = 16; o; o >>= 1) m = fmaxf(m, __shfl_xor_sync(0xffffffffu, m, o));
            float s = 0.f;
            #pragma unroll
            for (int jj = 0; jj < 4; jj++) { pr[q][jj] = __expf(a[q][jj] - m); s += pr[q][jj]; }
            #pragma unroll
            for (int o = 16; o; o >>= 1) s += __shfl_xor_sync(0xffffffffu, s, o);
            float inv = __frcp_rn(s);
            #pragma unroll
            for (int jj = 0; jj < 4; jj++) pr[q][jj] *= inv;
        }

        float ox[4], oy[4];
        #pragma unroll
        for (int q = 0; q < 4; q++) { ox[q] = 0.f; oy[q] = 0.f; }
        #pragma unroll
        for (int jj = 0; jj < 4; jj++) {
            for (int js = 0; js < 32; js++) {
                float2 vv = ((const float2*)(sV + (jj*32 + js)*64))[lane];
                #pragma unroll
                for (int q = 0; q < 4; q++) {
                    float w = __shfl_sync(0xffffffffu, pr[q][jj], js);
                    ox[q] += w * vv.x;
                    oy[q] += w * vv.y;
                }
            }
        }

        #pragma unroll
        for (int q = 0; q < 4; q++) {
            int g = sIdx[irow[q]];
            float* dst = out + ((size_t)bh*T + g)*D + 2*lane;
            atomicAdd(dst,     ox[q]);
            atomicAdd(dst + 1, oy[q]);
            if (lane == 0) atomicAdd(&g_count[(size_t)bh*T + g], 1);
        }
    }
}

// ---------------- K8: finalize out /= (count + 1e-5), warp per token, Markstein ----------------
__global__ void k_final(float* __restrict__ out) {
    int tok = blockIdx.x * (blockDim.x >> 5) + (threadIdx.x >> 5);
    int lane = threadIdx.x & 31;
    if (tok >= B*H*T) return;
    float dnm = (float)g_count[tok] + 1e-5f;
    float r = __frcp_rn(dnm);
    float2* p = (float2*)(out + (size_t)tok * D);
    float2 val = p[lane];
    val.x = fdiv_rn_m(val.x, dnm, r);
    val.y = fdiv_rn_m(val.y, dnm, r);
    p[lane] = val;
}

// ---------------- launch ----------------
extern "C" void kernel_launch(void* const* d_in, const int* in_sizes, int n_in,
                              void* d_out, int out_size) {
    const float* qk    = (const float*)d_in[0];
    const float* v     = (const float*)d_in[1];
    const float* means = (const float*)d_in[2];
    const float* rw    = (const float*)d_in[3];
    float* out = (float*)d_out;

    cudaFuncSetAttribute(k_attn, cudaFuncAttributeMaxDynamicSharedMemorySize, ATTN_SMEM);

    k_zero<<<2048, 256>>>(out);
    k_norm<<<(B*H*T + 255)/256, 256>>>(qk);
    k_buckets<<<BH*(T/64), 256>>>(means);
    k_sumsC<<<BH*2, 1024>>>();
    k_meansupd<<<(H*C + 255)/256, 256>>>(means);
    k_dists<<<BH*(T/64), 256>>>();
    k_topk<<<BH*C, 256>>>();
    k_attn<<<BH*NC, 256, ATTN_SMEM>>>(qk, v, rw, out);
    k_final<<<(B*H*T)/8, 256>>>(out);
}

// round 14
// speedup vs baseline: 1.3398x; 1.3398x over previous
#include <cuda_runtime.h>
#include <math.h>

#define B 4
#define H 16
#define T 8192
#define D 64
#define C 64
#define W 128
#define NC 64
#define BH (B*H)

// ---------------- scratch ----------------
__device__ float g_knorm[(size_t)B*H*T*D];
__device__ float g_dists[(size_t)B*H*C*T];
__device__ unsigned char g_bucketsB[B*H*T];
__device__ float g_part[(size_t)B*H*C*D];
__device__ int   g_bins[H*C];
__device__ float g_meansu[H*C*D];
__device__ int   g_indices[B*H*T];
__device__ int   g_count[B*H*T];

// Correctly-rounded division via Markstein sequence (r = __frcp_rn(n)).
__device__ __forceinline__ float fdiv_rn_m(float x, float n, float r) {
    float q = __fmul_rn(x, r);
    float e = __fmaf_rn(-q, n, x);
    return __fmaf_rn(e, r, q);
}

// ---------------- K0: zero accumulators ----------------
__global__ void k_zero(float* __restrict__ out) {
    size_t i = (size_t)blockIdx.x * blockDim.x + threadIdx.x;
    size_t stride = (size_t)gridDim.x * blockDim.x;
    const size_t NOUT = (size_t)B*H*T*D;
    for (size_t p = i; p < NOUT; p += stride) out[p] = 0.f;
    for (size_t p = i; p < (size_t)B*H*T; p += stride) g_count[p] = 0;
    for (size_t p = i; p < (size_t)H*C; p += stride) g_bins[p] = 0;
}

// ---------------- K1: k_norm (bit-exact: sequential fused fma ssq; Markstein div) ----------------
__global__ void k_norm(const float* __restrict__ qk) {
    int tok = blockIdx.x * blockDim.x + threadIdx.x;
    if (tok >= B*H*T) return;
    const float4* src = (const float4*)(qk + (size_t)tok * D);
    float v[64];
    #pragma unroll
    for (int i = 0; i < 16; i++) {
        float4 q = src[i];
        v[4*i+0] = q.x; v[4*i+1] = q.y; v[4*i+2] = q.z; v[4*i+3] = q.w;
    }
    float s = 0.f;
    #pragma unroll
    for (int d = 0; d < 64; d++) s = __fmaf_rn(v[d], v[d], s);
    float n = fmaxf(__fsqrt_rn(s), 1e-12f);
    float r = __frcp_rn(n);
    float4* dst = (float4*)(g_knorm + (size_t)tok * D);
    #pragma unroll
    for (int i = 0; i < 16; i++) {
        float4 o;
        o.x = fdiv_rn_m(v[4*i+0], n, r);
        o.y = fdiv_rn_m(v[4*i+1], n, r);
        o.z = fdiv_rn_m(v[4*i+2], n, r);
        o.w = fdiv_rn_m(v[4*i+3], n, r);
        dst[i] = o;
    }
}

// ---------------- K2: buckets = argmax_c (k_norm . means)  [R12 version] ----------------
__global__ void k_buckets(const float* __restrict__ means) {
    __shared__ float sM[64*68];   // [d][c]
    __shared__ float sT[64*68];   // [d][tok]
    int blk = blockIdx.x;
    int bh = blk / (T/64);
    int chunk = blk % (T/64);
    int h = bh % H;
    int tid = threadIdx.x;

    for (int i = tid; i < C*D; i += 256) {
        int c = i >> 6, d = i & 63;
        sM[d*68 + c] = means[(size_t)h*C*D + i];
    }
    size_t base = ((size_t)bh*T + (size_t)chunk*64) * D;
    for (int i = tid; i < 64*D; i += 256) {
        int r = i >> 6, d = i & 63;
        sT[d*68 + r] = g_knorm[base + i];
    }
    __syncthreads();

    int tx = tid & 15, ty = tid >> 4;
    int tok0 = ty*4, c0 = tx*4;
    float a[4][4];
    #pragma unroll
    for (int r = 0; r < 4; r++)
        #pragma unroll
        for (int cc = 0; cc < 4; cc++) a[r][cc] = 0.f;

    #pragma unroll 8
    for (int d = 0; d < 64; d++) {
        float4 q4 = *(const float4*)&sT[d*68 + tok0];
        float4 m4 = *(const float4*)&sM[d*68 + c0];
        float qv[4] = {q4.x, q4.y, q4.z, q4.w};
        float mv[4] = {m4.x, m4.y, m4.z, m4.w};
        #pragma unroll
        for (int r = 0; r < 4; r++)
            #pragma unroll
            for (int cc = 0; cc < 4; cc++)
                a[r][cc] = __fmaf_rn(qv[r], mv[cc], a[r][cc]);
    }
    __syncthreads();

    float* sSim = sM;
    #pragma unroll
    for (int r = 0; r < 4; r++)
        #pragma unroll
        for (int cc = 0; cc < 4; cc++)
            sSim[(tok0 + r)*64 + c0 + cc] = a[r][cc];
    __syncthreads();

    if (tid < 64) {
        float best = -1e30f; int bi = 0;
        #pragma unroll 8
        for (int c = 0; c < C; c++) {
            float s = sSim[tid*64 + c];
            if (s > best) { best = s; bi = c; }   // strict > : first index on ties
        }
        g_bucketsB[(size_t)bh*T + chunk*64 + tid] = (unsigned char)bi;
    }
}

// ---------------- K3: cluster sums — byte buckets, vcmpeq4 scan (t-ascending chains) ----------------
__global__ __launch_bounds__(1024, 1) void k_sumsC() {
    __shared__ unsigned int sb[T/4];      // 8 KB
    int bh = blockIdx.x >> 1;
    int half = blockIdx.x & 1;
    int tid = threadIdx.x;
    int lane = tid & 31, wid = tid >> 5;
    size_t base = (size_t)bh * T;
    for (int i = tid; i < T/16; i += 1024)
        ((uint4*)sb)[i] = ((const uint4*)(g_bucketsB + base))[i];
    __syncthreads();

    int c = half*32 + wid;
    unsigned int cc = (unsigned int)c * 0x01010101u;
    float ax = 0.f, ay = 0.f;
    int cnt = 0;

    #define ADDTOK(tt) { float2 xv = ((const float2*)(g_knorm + (base + (tt))*D))[lane]; \
                         ax = __fadd_rn(ax, xv.x); ay = __fadd_rn(ay, xv.y); cnt++; }
    #define SCANW(u, t0) { unsigned int m = __vcmpeq4((u), cc); \
        if (m) { if (m & 0x000000FFu) ADDTOK((t0)+0); if (m & 0x0000FF00u) ADDTOK((t0)+1); \
                 if (m & 0x00FF0000u) ADDTOK((t0)+2); if (m & 0xFF000000u) ADDTOK((t0)+3); } }

    for (int t = 0; t < T; t += 16) {
        uint4 w = *(const uint4*)&sb[t >> 2];
        SCANW(w.x, t+0);
        SCANW(w.y, t+4);
        SCANW(w.z, t+8);
        SCANW(w.w, t+12);
    }
    #undef SCANW
    #undef ADDTOK

    float2 o; o.x = ax; o.y = ay;
    ((float2*)(g_part + ((size_t)bh*C + c) * D))[lane] = o;
    if (lane == 0) atomicAdd(&g_bins[(bh & (H-1))*C + c], cnt);
}

// ---------------- K4: means_upd (b-ascending combine + fused ssq + Markstein div) ----------------
__global__ void k_meansupd(const float* __restrict__ means) {
    int inst = blockIdx.x * blockDim.x + threadIdx.x;
    if (inst >= H*C) return;
    float sv[64];
    #pragma unroll 4
    for (int d = 0; d < D; d++) {
        float s = g_part[((size_t)0*1024 + inst)*D + d];
        s = __fadd_rn(s, g_part[((size_t)1*1024 + inst)*D + d]);
        s = __fadd_rn(s, g_part[((size_t)2*1024 + inst)*D + d]);
        s = __fadd_rn(s, g_part[((size_t)3*1024 + inst)*D + d]);
        sv[d] = s;
    }
    float ssq = 0.f;
    #pragma unroll
    for (int d = 0; d < D; d++) ssq = __fmaf_rn(sv[d], sv[d], ssq);
    float n = fmaxf(__fsqrt_rn(ssq), 1e-12f);
    float r = __frcp_rn(n);
    bool empty = (g_bins[inst] == 0);
    #pragma unroll 4
    for (int d = 0; d < D; d++) {
        float o = empty ? means[(size_t)inst*D + d] : fdiv_rn_m(sv[d], n, r);
        g_meansu[(size_t)inst*D + d] = o;
    }
}

// ---------------- K5: dists (b,h,c,t) = k_norm . means_upd^T  [R12 version] ----------------
__global__ void k_dists() {
    __shared__ float sM[64*68];
    __shared__ float sT[64*68];
    int blk = blockIdx.x;
    int bh = blk / (T/64);
    int chunk = blk % (T/64);
    int h = bh % H;
    int tid = threadIdx.x;

    for (int i = tid; i < C*D; i += 256) {
        int c = i >> 6, d = i & 63;
        sM[d*68 + c] = g_meansu[(size_t)h*C*D + i];
    }
    size_t base = ((size_t)bh*T + (size_t)chunk*64) * D;
    for (int i = tid; i < 64*D; i += 256) {
        int r = i >> 6, d = i & 63;
        sT[d*68 + r] = g_knorm[base + i];
    }
    __syncthreads();

    int tx = tid & 15, ty = tid >> 4;
    int tok0 = ty*4, c0 = tx*4;
    float a[4][4];
    #pragma unroll
    for (int r = 0; r < 4; r++)
        #pragma unroll
        for (int cc = 0; cc < 4; cc++) a[r][cc] = 0.f;

    #pragma unroll 8
    for (int d = 0; d < 64; d++) {
        float4 q4 = *(const float4*)&sT[d*68 + tok0];
        float4 m4 = *(const float4*)&sM[d*68 + c0];
        float qv[4] = {q4.x, q4.y, q4.z, q4.w};
        float mv[4] = {m4.x, m4.y, m4.z, m4.w};
        #pragma unroll
        for (int r = 0; r < 4; r++)
            #pragma unroll
            for (int cc = 0; cc < 4; cc++)
                a[r][cc] = __fmaf_rn(qv[r], mv[cc], a[r][cc]);
    }
    __syncthreads();

    float* sSim = sM;    // alias: [c][tok] for coalesced store
    #pragma unroll
    for (int r = 0; r < 4; r++)
        #pragma unroll
        for (int cc = 0; cc < 4; cc++)
            sSim[(c0 + cc)*64 + tok0 + r] = a[r][cc];
    __syncthreads();

    for (int i = tid; i < C*64; i += 256) {
        int c = i >> 6, t = i & 63;
        g_dists[((size_t)bh*C + c)*T + (size_t)chunk*64 + t] = sSim[i];
    }
}

// ---------------- K6: top-128 per (b,h,c): radix select + bitonic index sort ----------------
__global__ void k_topk() {
    __shared__ unsigned int keys[T];
    __shared__ unsigned int hist[256];
    __shared__ unsigned int sh_pref;
    __shared__ int sh_k;
    __shared__ int outbuf[W];
    __shared__ int gtc;
    __shared__ int eqbase;
    __shared__ int warpTot[8];

    int inst = blockIdx.x;
    int bh = inst / C;
    int c = inst % C;
    int tid = threadIdx.x, lane = tid & 31, wid = tid >> 5;

    const float* row = g_dists + (size_t)inst * T;
    for (int i = tid; i < T; i += 256) {
        unsigned int u = __float_as_uint(row[i]);
        keys[i] = (u & 0x80000000u) ? ~u : (u | 0x80000000u);
    }
    __syncthreads();

    unsigned int prefix = 0; int k = 128;
    for (int sh = 24; sh >= 0; sh -= 8) {
        hist[tid] = 0;
        __syncthreads();
        unsigned int hmask = (sh == 24) ? 0u : (0xFFFFFFFFu << (sh + 8));
        for (int i = tid; i < T; i += 256) {
            unsigned int kk = keys[i];
            if ((kk & hmask) == prefix) atomicAdd(&hist[(kk >> sh) & 255], 1u);
        }
        __syncthreads();
        if (tid == 0) {
            int cum = 0;
            for (int bkt = 255; bkt >= 0; bkt--) {
                cum += (int)hist[bkt];
                if (cum >= k) {
                    sh_pref = prefix | ((unsigned int)bkt << sh);
                    sh_k = k - (cum - (int)hist[bkt]);
                    break;
                }
            }
        }
        __syncthreads();
        prefix = sh_pref; k = sh_k;
        __syncthreads();
    }
    unsigned int Tkey = prefix;
    int k_rem = k;
    int count_gt = 128 - k_rem;

    if (tid == 0) { gtc = 0; eqbase = 0; }
    __syncthreads();

    for (int i = tid; i < T; i += 256) {
        if (keys[i] > Tkey) {
            int p = atomicAdd(&gtc, 1);
            outbuf[p] = i;
        }
    }
    __syncthreads();

    for (int ch = 0; ch < T; ch += 256) {
        int i = ch + tid;
        bool eq = (keys[i] == Tkey);
        unsigned int bal = __ballot_sync(0xffffffffu, eq);
        int wpre = __popc(bal & ((1u << lane) - 1u));
        if (lane == 0) warpTot[wid] = __popc(bal);
        __syncthreads();
        int base = eqbase;
        int woff = 0;
        for (int w = 0; w < wid; w++) woff += warpTot[w];
        if (eq) {
            int rank = base + woff + wpre;
            if (rank < k_rem) outbuf[count_gt + rank] = i;
        }
        __syncthreads();
        if (tid == 0) {
            int tot = 0;
            for (int w = 0; w < 8; w++) tot += warpTot[w];
            eqbase += tot;
        }
        __syncthreads();
        if (eqbase >= k_rem) break;
    }

    for (int size = 2; size <= 128; size <<= 1) {
        for (int stride = size >> 1; stride > 0; stride >>= 1) {
            __syncthreads();
            if (tid < 128) {
                int partner = tid ^ stride;
                if (partner > tid) {
                    bool up = ((tid & size) == 0);
                    int a = outbuf[tid], b2 = outbuf[partner];
                    if ((a > b2) == up) { outbuf[tid] = b2; outbuf[partner] = a; }
                }
            }
        }
    }
    __syncthreads();
    if (tid < 128) g_indices[(size_t)bh*T + c*W + tid] = outbuf[tid];
}

// ---------------- K7: windowed attention — no sK tile (kk = Q/||Q|| via ninv), 2 blocks/SM ----------------
// smem: sQ[128][66], sV[128][64], sR[128][66], ninv[128], idx[128] = ~99 KB
#define ATTN_SMEM ((128*66 + 128*64 + 128*66) * 4 + 128*4 + 128*4)

__global__ __launch_bounds__(256, 2)
void k_attn(const float* __restrict__ qk, const float* __restrict__ v,
            const float* __restrict__ rw, float* __restrict__ out) {
    extern __shared__ float sm[];
    float* sQ = sm;                      // [128][66]
    float* sV = sQ + 128*66;             // [128][64]
    float* sR = sV + 128*64;             // [128][66]
    float* sN = sR + 128*66;             // [128] 1/||Q_j||
    int*   sIdx = (int*)(sN + 128);

    int inst = blockIdx.x;
    int bh = inst / NC;
    int n  = inst % NC;
    int h  = bh % H;
    int tid = threadIdx.x, lane = tid & 31, wid = tid >> 5;

    if (tid < 128) sIdx[tid] = g_indices[(size_t)bh*T + n*W + tid];
    __syncthreads();

    for (int r = wid; r < 128; r += 8) {
        int g = sIdx[r];
        size_t off = ((size_t)bh*T + g) * D;
        float2 a = ((const float2*)(qk + off))[lane];
        float2 c2 = ((const float2*)(v + off))[lane];
        sQ[r*66 + 2*lane] = a.x;  sQ[r*66 + 2*lane + 1] = a.y;
        sV[r*64 + 2*lane] = c2.x; sV[r*64 + 2*lane + 1] = c2.y;
        float2 rr = ((const float2*)(rw + ((size_t)r*H + h)*D))[lane];
        sR[r*66 + 2*lane] = rr.x; sR[r*66 + 2*lane + 1] = rr.y;
        // per-row inverse norm (tolerant path: ulps vs reference kk division)
        float ssq = a.x*a.x + a.y*a.y;
        #pragma unroll
        for (int o = 16; o; o >>= 1) ssq += __shfl_xor_sync(0xffffffffu, ssq, o);
        if (lane == 0) sN[r] = __frcp_rn(fmaxf(__fsqrt_rn(ssq), 1e-12f));
    }
    __syncthreads();

    const float scale = 0.125f;

    for (int p = 0; p < 4; p++) {
        int irow[4];
        #pragma unroll
        for (int q = 0; q < 4; q++) irow[q] = wid + 8*q + 32*p;

        float a[4][4];
        #pragma unroll
        for (int q = 0; q < 4; q++)
            #pragma unroll
            for (int jj = 0; jj < 4; jj++) a[q][jj] = 0.f;

        // dots(raw) = Q_i . Q_j
        #pragma unroll 4
        for (int d2 = 0; d2 < 32; d2++) {
            float2 qv[4];
            #pragma unroll
            for (int q = 0; q < 4; q++) qv[q] = *(const float2*)&sQ[irow[q]*66 + 2*d2];
            #pragma unroll
            for (int jj = 0; jj < 4; jj++) {
                float2 kv = *(const float2*)&sQ[(lane + 32*jj)*66 + 2*d2];
                #pragma unroll
                for (int q = 0; q < 4; q++)
                    a[q][jj] += qv[q].x*kv.x + qv[q].y*kv.y;
            }
        }
        // column normalization: dots = (Q_i.Q_j) / ||Q_j||
        float nv[4];
        #pragma unroll
        for (int jj = 0; jj < 4; jj++) nv[jj] = sN[lane + 32*jj];
        #pragma unroll
        for (int q = 0; q < 4; q++)
            #pragma unroll
            for (int jj = 0; jj < 4; jj++) a[q][jj] *= nv[jj];

        // rel: for j < i, += Q_i . rw[127 + j - i]  (hardware skips empty chunks)
        #pragma unroll
        for (int q = 0; q < 4; q++) {
            int i = irow[q];
            #pragma unroll
            for (int jj = 0; jj < 4; jj++) {
                int j = lane + 32*jj;
                if (j < i) {
                    int r = 127 + j - i;
                    float s = 0.f;
                    for (int d2 = 0; d2 < 32; d2++) {
                        float2 qq = *(const float2*)&sQ[i*66 + 2*d2];
                        float2 rr = *(const float2*)&sR[r*66 + 2*d2];
                        s += qq.x*rr.x + qq.y*rr.y;
                    }
                    a[q][jj] += s;
                }
            }
        }

        float pr[4][4];
        #pragma unroll
        for (int q = 0; q < 4; q++) {
            int i = irow[q];
            float m = -1e30f;
            #pragma unroll
            for (int jj = 0; jj < 4; jj++) {
                int j = lane + 32*jj;
                a[q][jj] = (j == i) ? -50000.0f : a[q][jj]*scale;
                m = fmaxf(m, a[q][jj]);
            }
            #pragma unroll
            for (int o = 16; o; o >>= 1) m = fmaxf(m, __shfl_xor_sync(0xffffffffu, m, o));
            float s = 0.f;
            #pragma unroll
            for (int jj = 0; jj < 4; jj++) { pr[q][jj] = __expf(a[q][jj] - m); s += pr[q][jj]; }
            #pragma unroll
            for (int o = 16; o; o >>= 1) s += __shfl_xor_sync(0xffffffffu, s, o);
            float inv = __frcp_rn(s);
            #pragma unroll
            for (int jj = 0; jj < 4; jj++) pr[q][jj] *= inv;
        }

        float ox[4], oy[4];
        #pragma unroll
        for (int q = 0; q < 4; q++) { ox[q] = 0.f; oy[q] = 0.f; }
        #pragma unroll
        for (int jj = 0; jj < 4; jj++) {
            for (int js = 0; js < 32; js++) {
                float2 vv = ((const float2*)(sV + (jj*32 + js)*64))[lane];
                #pragma unroll
                for (int q = 0; q < 4; q++) {
                    float w = __shfl_sync(0xffffffffu, pr[q][jj], js);
                    ox[q] += w * vv.x;
                    oy[q] += w * vv.y;
                }
            }
        }

        #pragma unroll
        for (int q = 0; q < 4; q++) {
            int g = sIdx[irow[q]];
            float* dst = out + ((size_t)bh*T + g)*D + 2*lane;
            atomicAdd(dst,     ox[q]);
            atomicAdd(dst + 1, oy[q]);
            if (lane == 0) atomicAdd(&g_count[(size_t)bh*T + g], 1);
        }
    }
}

// ---------------- K8: finalize out /= (count + 1e-5), warp per token, Markstein ----------------
__global__ void k_final(float* __restrict__ out) {
    int tok = blockIdx.x * (blockDim.x >> 5) + (threadIdx.x >> 5);
    int lane = threadIdx.x & 31;
    if (tok >= B*H*T) return;
    float dnm = (float)g_count[tok] + 1e-5f;
    float r = __frcp_rn(dnm);
    float2* p = (float2*)(out + (size_t)tok * D);
    float2 val = p[lane];
    val.x = fdiv_rn_m(val.x, dnm, r);
    val.y = fdiv_rn_m(val.y, dnm, r);
    p[lane] = val;
}

// ---------------- launch ----------------
extern "C" void kernel_launch(void* const* d_in, const int* in_sizes, int n_in,
                              void* d_out, int out_size) {
    const float* qk    = (const float*)d_in[0];
    const float* v     = (const float*)d_in[1];
    const float* means = (const float*)d_in[2];
    const float* rw    = (const float*)d_in[3];
    float* out = (float*)d_out;

    cudaFuncSetAttribute(k_attn, cudaFuncAttributeMaxDynamicSharedMemorySize, ATTN_SMEM);

    k_zero<<<2048, 256>>>(out);
    k_norm<<<(B*H*T + 255)/256, 256>>>(qk);
    k_buckets<<<BH*(T/64), 256>>>(means);
    k_sumsC<<<BH*2, 1024>>>();
    k_meansupd<<<(H*C + 255)/256, 256>>>(means);
    k_dists<<<BH*(T/64), 256>>>();
    k_topk<<<BH*C, 256>>>();
    k_attn<<<BH*NC, 256, ATTN_SMEM>>>(qk, v, rw, out);
    k_final<<<(B*H*T)/8, 256>>>(out);
}

// round 15
// speedup vs baseline: 1.3869x; 1.0351x over previous
#include <cuda_runtime.h>
#include <math.h>

#define B 4
#define H 16
#define T 8192
#define D 64
#define C 64
#define W 128
#define NC 64
#define BH (B*H)

// ---------------- scratch ----------------
__device__ float g_knorm[(size_t)B*H*T*D];
__device__ float g_dists[(size_t)B*H*C*T];
__device__ unsigned char g_bucketsB[B*H*T];
__device__ float g_part[(size_t)B*H*C*D];
__device__ int   g_bins[H*C];
__device__ float g_meansu[H*C*D];
__device__ int   g_indices[B*H*T];
__device__ int   g_count[B*H*T];

// Correctly-rounded division via Markstein sequence (r = __frcp_rn(n)).
__device__ __forceinline__ float fdiv_rn_m(float x, float n, float r) {
    float q = __fmul_rn(x, r);
    float e = __fmaf_rn(-q, n, x);
    return __fmaf_rn(e, r, q);
}

// ---------------- K0: zero accumulators ----------------
__global__ void k_zero(float* __restrict__ out) {
    size_t i = (size_t)blockIdx.x * blockDim.x + threadIdx.x;
    size_t stride = (size_t)gridDim.x * blockDim.x;
    const size_t NOUT = (size_t)B*H*T*D;
    for (size_t p = i; p < NOUT; p += stride) out[p] = 0.f;
    for (size_t p = i; p < (size_t)B*H*T; p += stride) g_count[p] = 0;
    for (size_t p = i; p < (size_t)H*C; p += stride) g_bins[p] = 0;
}

// ---------------- K1: k_norm (bit-exact: sequential fused fma ssq; Markstein div) ----------------
__global__ void k_norm(const float* __restrict__ qk) {
    int tok = blockIdx.x * blockDim.x + threadIdx.x;
    if (tok >= B*H*T) return;
    const float4* src = (const float4*)(qk + (size_t)tok * D);
    float v[64];
    #pragma unroll
    for (int i = 0; i < 16; i++) {
        float4 q = src[i];
        v[4*i+0] = q.x; v[4*i+1] = q.y; v[4*i+2] = q.z; v[4*i+3] = q.w;
    }
    float s = 0.f;
    #pragma unroll
    for (int d = 0; d < 64; d++) s = __fmaf_rn(v[d], v[d], s);
    float n = fmaxf(__fsqrt_rn(s), 1e-12f);
    float r = __frcp_rn(n);
    float4* dst = (float4*)(g_knorm + (size_t)tok * D);
    #pragma unroll
    for (int i = 0; i < 16; i++) {
        float4 o;
        o.x = fdiv_rn_m(v[4*i+0], n, r);
        o.y = fdiv_rn_m(v[4*i+1], n, r);
        o.z = fdiv_rn_m(v[4*i+2], n, r);
        o.w = fdiv_rn_m(v[4*i+3], n, r);
        dst[i] = o;
    }
}

// ---------------- K2: buckets = argmax_c (k_norm . means) ----------------
__global__ void k_buckets(const float* __restrict__ means) {
    __shared__ float sM[64*68];   // [d][c]
    __shared__ float sT[64*68];   // [d][tok]
    int blk = blockIdx.x;
    int bh = blk / (T/64);
    int chunk = blk % (T/64);
    int h = bh % H;
    int tid = threadIdx.x;

    for (int i = tid; i < C*D; i += 256) {
        int c = i >> 6, d = i & 63;
        sM[d*68 + c] = means[(size_t)h*C*D + i];
    }
    size_t base = ((size_t)bh*T + (size_t)chunk*64) * D;
    for (int i = tid; i < 64*D; i += 256) {
        int r = i >> 6, d = i & 63;
        sT[d*68 + r] = g_knorm[base + i];
    }
    __syncthreads();

    int tx = tid & 15, ty = tid >> 4;
    int tok0 = ty*4, c0 = tx*4;
    float a[4][4];
    #pragma unroll
    for (int r = 0; r < 4; r++)
        #pragma unroll
        for (int cc = 0; cc < 4; cc++) a[r][cc] = 0.f;

    #pragma unroll 8
    for (int d = 0; d < 64; d++) {
        float4 q4 = *(const float4*)&sT[d*68 + tok0];
        float4 m4 = *(const float4*)&sM[d*68 + c0];
        float qv[4] = {q4.x, q4.y, q4.z, q4.w};
        float mv[4] = {m4.x, m4.y, m4.z, m4.w};
        #pragma unroll
        for (int r = 0; r < 4; r++)
            #pragma unroll
            for (int cc = 0; cc < 4; cc++)
                a[r][cc] = __fmaf_rn(qv[r], mv[cc], a[r][cc]);
    }
    __syncthreads();

    float* sSim = sM;
    #pragma unroll
    for (int r = 0; r < 4; r++)
        #pragma unroll
        for (int cc = 0; cc < 4; cc++)
            sSim[(tok0 + r)*64 + c0 + cc] = a[r][cc];
    __syncthreads();

    if (tid < 64) {
        float best = -1e30f; int bi = 0;
        #pragma unroll 8
        for (int c = 0; c < C; c++) {
            float s = sSim[tid*64 + c];
            if (s > best) { best = s; bi = c; }   // strict > : first index on ties
        }
        g_bucketsB[(size_t)bh*T + chunk*64 + tid] = (unsigned char)bi;
    }
}

// ---------------- K3: cluster sums — byte buckets, vcmpeq4 scan (t-ascending chains) ----------------
__global__ __launch_bounds__(1024, 1) void k_sumsC() {
    __shared__ unsigned int sb[T/4];      // 8 KB
    int bh = blockIdx.x >> 1;
    int half = blockIdx.x & 1;
    int tid = threadIdx.x;
    int lane = tid & 31, wid = tid >> 5;
    size_t base = (size_t)bh * T;
    for (int i = tid; i < T/16; i += 1024)
        ((uint4*)sb)[i] = ((const uint4*)(g_bucketsB + base))[i];
    __syncthreads();

    int c = half*32 + wid;
    unsigned int cc = (unsigned int)c * 0x01010101u;
    float ax = 0.f, ay = 0.f;
    int cnt = 0;

    #define ADDTOK(tt) { float2 xv = ((const float2*)(g_knorm + (base + (tt))*D))[lane]; \
                         ax = __fadd_rn(ax, xv.x); ay = __fadd_rn(ay, xv.y); cnt++; }
    #define SCANW(u, t0) { unsigned int m = __vcmpeq4((u), cc); \
        if (m) { if (m & 0x000000FFu) ADDTOK((t0)+0); if (m & 0x0000FF00u) ADDTOK((t0)+1); \
                 if (m & 0x00FF0000u) ADDTOK((t0)+2); if (m & 0xFF000000u) ADDTOK((t0)+3); } }

    for (int t = 0; t < T; t += 16) {
        uint4 w = *(const uint4*)&sb[t >> 2];
        SCANW(w.x, t+0);
        SCANW(w.y, t+4);
        SCANW(w.z, t+8);
        SCANW(w.w, t+12);
    }
    #undef SCANW
    #undef ADDTOK

    float2 o; o.x = ax; o.y = ay;
    ((float2*)(g_part + ((size_t)bh*C + c) * D))[lane] = o;
    if (lane == 0) atomicAdd(&g_bins[(bh & (H-1))*C + c], cnt);
}

// ---------------- K4: means_upd (b-ascending combine + fused ssq + Markstein div) ----------------
__global__ void k_meansupd(const float* __restrict__ means) {
    int inst = blockIdx.x * blockDim.x + threadIdx.x;
    if (inst >= H*C) return;
    float sv[64];
    #pragma unroll 4
    for (int d = 0; d < D; d++) {
        float s = g_part[((size_t)0*1024 + inst)*D + d];
        s = __fadd_rn(s, g_part[((size_t)1*1024 + inst)*D + d]);
        s = __fadd_rn(s, g_part[((size_t)2*1024 + inst)*D + d]);
        s = __fadd_rn(s, g_part[((size_t)3*1024 + inst)*D + d]);
        sv[d] = s;
    }
    float ssq = 0.f;
    #pragma unroll
    for (int d = 0; d < D; d++) ssq = __fmaf_rn(sv[d], sv[d], ssq);
    float n = fmaxf(__fsqrt_rn(ssq), 1e-12f);
    float r = __frcp_rn(n);
    bool empty = (g_bins[inst] == 0);
    #pragma unroll 4
    for (int d = 0; d < D; d++) {
        float o = empty ? means[(size_t)inst*D + d] : fdiv_rn_m(sv[d], n, r);
        g_meansu[(size_t)inst*D + d] = o;
    }
}

// ---------------- K5: dists (b,h,c,t) = k_norm . means_upd^T ----------------
__global__ void k_dists() {
    __shared__ float sM[64*68];
    __shared__ float sT[64*68];
    int blk = blockIdx.x;
    int bh = blk / (T/64);
    int chunk = blk % (T/64);
    int h = bh % H;
    int tid = threadIdx.x;

    for (int i = tid; i < C*D; i += 256) {
        int c = i >> 6, d = i & 63;
        sM[d*68 + c] = g_meansu[(size_t)h*C*D + i];
    }
    size_t base = ((size_t)bh*T + (size_t)chunk*64) * D;
    for (int i = tid; i < 64*D; i += 256) {
        int r = i >> 6, d = i & 63;
        sT[d*68 + r] = g_knorm[base + i];
    }
    __syncthreads();

    int tx = tid & 15, ty = tid >> 4;
    int tok0 = ty*4, c0 = tx*4;
    float a[4][4];
    #pragma unroll
    for (int r = 0; r < 4; r++)
        #pragma unroll
        for (int cc = 0; cc < 4; cc++) a[r][cc] = 0.f;

    #pragma unroll 8
    for (int d = 0; d < 64; d++) {
        float4 q4 = *(const float4*)&sT[d*68 + tok0];
        float4 m4 = *(const float4*)&sM[d*68 + c0];
        float qv[4] = {q4.x, q4.y, q4.z, q4.w};
        float mv[4] = {m4.x, m4.y, m4.z, m4.w};
        #pragma unroll
        for (int r = 0; r < 4; r++)
            #pragma unroll
            for (int cc = 0; cc < 4; cc++)
                a[r][cc] = __fmaf_rn(qv[r], mv[cc], a[r][cc]);
    }
    __syncthreads();

    float* sSim = sM;    // alias: [c][tok] for coalesced store
    #pragma unroll
    for (int r = 0; r < 4; r++)
        #pragma unroll
        for (int cc = 0; cc < 4; cc++)
            sSim[(c0 + cc)*64 + tok0 + r] = a[r][cc];
    __syncthreads();

    for (int i = tid; i < C*64; i += 256) {
        int c = i >> 6, t = i & 63;
        g_dists[((size_t)bh*C + c)*T + (size_t)chunk*64 + t] = sSim[i];
    }
}

// ---------------- K6: top-128 per (b,h,c): radix select, REGISTER-resident keys ----------------
__global__ void k_topk() {
    __shared__ unsigned int hist[256];
    __shared__ unsigned int sh_pref;
    __shared__ int sh_k;
    __shared__ int outbuf[W];
    __shared__ int gtc;
    __shared__ int eqbase;
    __shared__ int warpTot[8];

    int inst = blockIdx.x;
    int bh = inst / C;
    int c = inst % C;
    int tid = threadIdx.x, lane = tid & 31, wid = tid >> 5;

    // keys in registers: element i = 256*k + tid  (same index mapping as before)
    const float* row = g_dists + (size_t)inst * T;
    unsigned int key[32];
    #pragma unroll
    for (int k = 0; k < 32; k++) {
        unsigned int u = __float_as_uint(row[256*k + tid]);
        key[k] = (u & 0x80000000u) ? ~u : (u | 0x80000000u);  // monotone float->uint
    }

    unsigned int prefix = 0; int k = 128;
    for (int sh = 24; sh >= 0; sh -= 8) {
        hist[tid] = 0;
        __syncthreads();
        unsigned int hmask = (sh == 24) ? 0u : (0xFFFFFFFFu << (sh + 8));
        #pragma unroll
        for (int q = 0; q < 32; q++) {
            unsigned int kk = key[q];
            if ((kk & hmask) == prefix) atomicAdd(&hist[(kk >> sh) & 255], 1u);
        }
        __syncthreads();
        if (tid == 0) {
            int cum = 0;
            for (int bkt = 255; bkt >= 0; bkt--) {
                cum += (int)hist[bkt];
                if (cum >= k) {
                    sh_pref = prefix | ((unsigned int)bkt << sh);
                    sh_k = k - (cum - (int)hist[bkt]);
                    break;
                }
            }
        }
        __syncthreads();
        prefix = sh_pref; k = sh_k;
        __syncthreads();
    }
    unsigned int Tkey = prefix;
    int k_rem = k;
    int count_gt = 128 - k_rem;

    if (tid == 0) { gtc = 0; eqbase = 0; }
    __syncthreads();

    // strictly-greater (order irrelevant; indices sorted later)
    #pragma unroll
    for (int q = 0; q < 32; q++) {
        if (key[q] > Tkey) {
            int p = atomicAdd(&gtc, 1);
            outbuf[p] = 256*q + tid;
        }
    }
    __syncthreads();

    // equal: ordered chunked scan -> smallest indices first (matches top_k tie-break)
    for (int ch = 0; ch < 32; ch++) {
        bool eq = (key[ch] == Tkey);
        unsigned int bal = __ballot_sync(0xffffffffu, eq);
        int wpre = __popc(bal & ((1u << lane) - 1u));
        if (lane == 0) warpTot[wid] = __popc(bal);
        __syncthreads();
        int base = eqbase;
        int woff = 0;
        for (int w = 0; w < wid; w++) woff += warpTot[w];
        if (eq) {
            int rank = base + woff + wpre;
            if (rank < k_rem) outbuf[count_gt + rank] = 256*ch + tid;
        }
        __syncthreads();
        if (tid == 0) {
            int tot = 0;
            for (int w = 0; w < 8; w++) tot += warpTot[w];
            eqbase += tot;
        }
        __syncthreads();
        if (eqbase >= k_rem) break;
    }

    // bitonic sort 128 ints ascending
    for (int size = 2; size <= 128; size <<= 1) {
        for (int stride = size >> 1; stride > 0; stride >>= 1) {
            __syncthreads();
            if (tid < 128) {
                int partner = tid ^ stride;
                if (partner > tid) {
                    bool up = ((tid & size) == 0);
                    int a = outbuf[tid], b2 = outbuf[partner];
                    if ((a > b2) == up) { outbuf[tid] = b2; outbuf[partner] = a; }
                }
            }
        }
    }
    __syncthreads();
    if (tid < 128) g_indices[(size_t)bh*T + c*W + tid] = outbuf[tid];
}

// ---------------- K7: windowed attention — fused dots+rel d-loop, no sK tile, 2 blocks/SM ----------------
// smem: sQ[128][66], sV[128][64], sR[128][66], ninv[128], idx[128] = ~99 KB
#define ATTN_SMEM ((128*66 + 128*64 + 128*66) * 4 + 128*4 + 128*4)

__global__ __launch_bounds__(256, 2)
void k_attn(const float* __restrict__ qk, const float* __restrict__ v,
            const float* __restrict__ rw, float* __restrict__ out) {
    extern __shared__ float sm[];
    float* sQ = sm;                      // [128][66]
    float* sV = sQ + 128*66;             // [128][64]
    float* sR = sV + 128*64;             // [128][66]
    float* sN = sR + 128*66;             // [128] 1/||Q_j||
    int*   sIdx = (int*)(sN + 128);

    int inst = blockIdx.x;
    int bh = inst / NC;
    int n  = inst % NC;
    int h  = bh % H;
    int tid = threadIdx.x, lane = tid & 31, wid = tid >> 5;

    if (tid < 128) sIdx[tid] = g_indices[(size_t)bh*T + n*W + tid];
    __syncthreads();

    for (int r = wid; r < 128; r += 8) {
        int g = sIdx[r];
        size_t off = ((size_t)bh*T + g) * D;
        float2 a = ((const float2*)(qk + off))[lane];
        float2 c2 = ((const float2*)(v + off))[lane];
        sQ[r*66 + 2*lane] = a.x;  sQ[r*66 + 2*lane + 1] = a.y;
        sV[r*64 + 2*lane] = c2.x; sV[r*64 + 2*lane + 1] = c2.y;
        float2 rr = ((const float2*)(rw + ((size_t)r*H + h)*D))[lane];
        sR[r*66 + 2*lane] = rr.x; sR[r*66 + 2*lane + 1] = rr.y;
        // per-row inverse norm (tolerant path)
        float ssq = a.x*a.x + a.y*a.y;
        #pragma unroll
        for (int o = 16; o; o >>= 1) ssq += __shfl_xor_sync(0xffffffffu, ssq, o);
        if (lane == 0) sN[r] = __frcp_rn(fmaxf(__fsqrt_rn(ssq), 1e-12f));
    }
    __syncthreads();

    const float scale = 0.125f;

    for (int p = 0; p < 4; p++) {
        int irow[4];
        #pragma unroll
        for (int q = 0; q < 4; q++) irow[q] = wid + 8*q + 32*p;

        float a[4][4], rca[4][4];
        #pragma unroll
        for (int q = 0; q < 4; q++)
            #pragma unroll
            for (int jj = 0; jj < 4; jj++) { a[q][jj] = 0.f; rca[q][jj] = 0.f; }

        // fused: dots(raw) = Q_i.Q_j  AND  rel = Q_i . rw[127+j-i] (reuses qv regs)
        #pragma unroll 2
        for (int d2 = 0; d2 < 32; d2++) {
            float2 qv[4];
            #pragma unroll
            for (int q = 0; q < 4; q++) qv[q] = *(const float2*)&sQ[irow[q]*66 + 2*d2];
            #pragma unroll
            for (int jj = 0; jj < 4; jj++) {
                float2 kv = *(const float2*)&sQ[(lane + 32*jj)*66 + 2*d2];
                #pragma unroll
                for (int q = 0; q < 4; q++)
                    a[q][jj] += qv[q].x*kv.x + qv[q].y*kv.y;
            }
            #pragma unroll
            for (int q = 0; q < 4; q++) {
                #pragma unroll
                for (int jj = 0; jj < 4; jj++) {
                    int j = lane + 32*jj;
                    if (j < irow[q]) {
                        float2 rr = *(const float2*)&sR[(127 + j - irow[q])*66 + 2*d2];
                        rca[q][jj] += qv[q].x*rr.x + qv[q].y*rr.y;
                    }
                }
            }
        }

        // combine: dots/||Q_j|| + rel
        float nv[4];
        #pragma unroll
        for (int jj = 0; jj < 4; jj++) nv[jj] = sN[lane + 32*jj];
        #pragma unroll
        for (int q = 0; q < 4; q++)
            #pragma unroll
            for (int jj = 0; jj < 4; jj++)
                a[q][jj] = a[q][jj]*nv[jj] + rca[q][jj];

        float pr[4][4];
        #pragma unroll
        for (int q = 0; q < 4; q++) {
            int i = irow[q];
            float m = -1e30f;
            #pragma unroll
            for (int jj = 0; jj < 4; jj++) {
                int j = lane + 32*jj;
                a[q][jj] = (j == i) ? -50000.0f : a[q][jj]*scale;
                m = fmaxf(m, a[q][jj]);
            }
            #pragma unroll
            for (int o = 16; o; o >>= 1) m = fmaxf(m, __shfl_xor_sync(0xffffffffu, m, o));
            float s = 0.f;
            #pragma unroll
            for (int jj = 0; jj < 4; jj++) { pr[q][jj] = __expf(a[q][jj] - m); s += pr[q][jj]; }
            #pragma unroll
            for (int o = 16; o; o >>= 1) s += __shfl_xor_sync(0xffffffffu, s, o);
            float inv = __frcp_rn(s);
            #pragma unroll
            for (int jj = 0; jj < 4; jj++) pr[q][jj] *= inv;
        }

        float ox[4], oy[4];
        #pragma unroll
        for (int q = 0; q < 4; q++) { ox[q] = 0.f; oy[q] = 0.f; }
        #pragma unroll
        for (int jj = 0; jj < 4; jj++) {
            for (int js = 0; js < 32; js++) {
                float2 vv = ((const float2*)(sV + (jj*32 + js)*64))[lane];
                #pragma unroll
                for (int q = 0; q < 4; q++) {
                    float w = __shfl_sync(0xffffffffu, pr[q][jj], js);
                    ox[q] += w * vv.x;
                    oy[q] += w * vv.y;
                }
            }
        }

        #pragma unroll
        for (int q = 0; q < 4; q++) {
            int g = sIdx[irow[q]];
            float* dst = out + ((size_t)bh*T + g)*D + 2*lane;
            atomicAdd(dst,     ox[q]);
            atomicAdd(dst + 1, oy[q]);
            if (lane == 0) atomicAdd(&g_count[(size_t)bh*T + g], 1);
        }
    }
}

// ---------------- K8: finalize out /= (count + 1e-5), warp per token, Markstein ----------------
__global__ void k_final(float* __restrict__ out) {
    int tok = blockIdx.x * (blockDim.x >> 5) + (threadIdx.x >> 5);
    int lane = threadIdx.x & 31;
    if (tok >= B*H*T) return;
    float dnm = (float)g_count[tok] + 1e-5f;
    float r = __frcp_rn(dnm);
    float2* p = (float2*)(out + (size_t)tok * D);
    float2 val = p[lane];
    val.x = fdiv_rn_m(val.x, dnm, r);
    val.y = fdiv_rn_m(val.y, dnm, r);
    p[lane] = val;
}

// ---------------- launch ----------------
extern "C" void kernel_launch(void* const* d_in, const int* in_sizes, int n_in,
                              void* d_out, int out_size) {
    const float* qk    = (const float*)d_in[0];
    const float* v     = (const float*)d_in[1];
    const float* means = (const float*)d_in[2];
    const float* rw    = (const float*)d_in[3];
    float* out = (float*)d_out;

    cudaFuncSetAttribute(k_attn, cudaFuncAttributeMaxDynamicSharedMemorySize, ATTN_SMEM);

    k_zero<<<2048, 256>>>(out);
    k_norm<<<(B*H*T + 255)/256, 256>>>(qk);
    k_buckets<<<BH*(T/64), 256>>>(means);
    k_sumsC<<<BH*2, 1024>>>();
    k_meansupd<<<(H*C + 255)/256, 256>>>(means);
    k_dists<<<BH*(T/64), 256>>>();
    k_topk<<<BH*C, 256>>>();
    k_attn<<<BH*NC, 256, ATTN_SMEM>>>(qk, v, rw, out);
    k_final<<<(B*H*T)/8, 256>>>(out);
}

// round 16
// speedup vs baseline: 1.4364x; 1.0357x over previous
#include <cuda_runtime.h>
#include <math.h>

#define B 4
#define H 16
#define T 8192
#define D 64
#define C 64
#define W 128
#define NC 64
#define BH (B*H)

// ---------------- scratch ----------------
__device__ float g_knorm[(size_t)B*H*T*D];
__device__ float g_dists[(size_t)B*H*C*T];
__device__ unsigned char g_bucketsB[B*H*T];
__device__ float g_part[(size_t)B*H*C*D];
__device__ int   g_bins[H*C];
__device__ float g_meansu[H*C*D];
__device__ int   g_indices[B*H*T];
__device__ int   g_count[B*H*T];

// Correctly-rounded division via Markstein sequence (r = __frcp_rn(n)).
__device__ __forceinline__ float fdiv_rn_m(float x, float n, float r) {
    float q = __fmul_rn(x, r);
    float e = __fmaf_rn(-q, n, x);
    return __fmaf_rn(e, r, q);
}

// ---------------- K0: zero accumulators ----------------
__global__ void k_zero(float* __restrict__ out) {
    size_t i = (size_t)blockIdx.x * blockDim.x + threadIdx.x;
    size_t stride = (size_t)gridDim.x * blockDim.x;
    const size_t NOUT = (size_t)B*H*T*D;
    for (size_t p = i; p < NOUT; p += stride) out[p] = 0.f;
    for (size_t p = i; p < (size_t)B*H*T; p += stride) g_count[p] = 0;
    for (size_t p = i; p < (size_t)H*C; p += stride) g_bins[p] = 0;
}

// ---------------- K1: k_norm (bit-exact: sequential fused fma ssq; Markstein div) ----------------
__global__ void k_norm(const float* __restrict__ qk) {
    int tok = blockIdx.x * blockDim.x + threadIdx.x;
    if (tok >= B*H*T) return;
    const float4* src = (const float4*)(qk + (size_t)tok * D);
    float v[64];
    #pragma unroll
    for (int i = 0; i < 16; i++) {
        float4 q = src[i];
        v[4*i+0] = q.x; v[4*i+1] = q.y; v[4*i+2] = q.z; v[4*i+3] = q.w;
    }
    float s = 0.f;
    #pragma unroll
    for (int d = 0; d < 64; d++) s = __fmaf_rn(v[d], v[d], s);
    float n = fmaxf(__fsqrt_rn(s), 1e-12f);
    float r = __frcp_rn(n);
    float4* dst = (float4*)(g_knorm + (size_t)tok * D);
    #pragma unroll
    for (int i = 0; i < 16; i++) {
        float4 o;
        o.x = fdiv_rn_m(v[4*i+0], n, r);
        o.y = fdiv_rn_m(v[4*i+1], n, r);
        o.z = fdiv_rn_m(v[4*i+2], n, r);
        o.w = fdiv_rn_m(v[4*i+3], n, r);
        dst[i] = o;
    }
}

// ---------------- K2: buckets = argmax_c (k_norm . means) ----------------
__global__ void k_buckets(const float* __restrict__ means) {
    __shared__ float sM[64*68];   // [d][c]
    __shared__ float sT[64*68];   // [d][tok]
    int blk = blockIdx.x;
    int bh = blk / (T/64);
    int chunk = blk % (T/64);
    int h = bh % H;
    int tid = threadIdx.x;

    for (int i = tid; i < C*D; i += 256) {
        int c = i >> 6, d = i & 63;
        sM[d*68 + c] = means[(size_t)h*C*D + i];
    }
    size_t base = ((size_t)bh*T + (size_t)chunk*64) * D;
    for (int i = tid; i < 64*D; i += 256) {
        int r = i >> 6, d = i & 63;
        sT[d*68 + r] = g_knorm[base + i];
    }
    __syncthreads();

    int tx = tid & 15, ty = tid >> 4;
    int tok0 = ty*4, c0 = tx*4;
    float a[4][4];
    #pragma unroll
    for (int r = 0; r < 4; r++)
        #pragma unroll
        for (int cc = 0; cc < 4; cc++) a[r][cc] = 0.f;

    #pragma unroll 8
    for (int d = 0; d < 64; d++) {
        float4 q4 = *(const float4*)&sT[d*68 + tok0];
        float4 m4 = *(const float4*)&sM[d*68 + c0];
        float qv[4] = {q4.x, q4.y, q4.z, q4.w};
        float mv[4] = {m4.x, m4.y, m4.z, m4.w};
        #pragma unroll
        for (int r = 0; r < 4; r++)
            #pragma unroll
            for (int cc = 0; cc < 4; cc++)
                a[r][cc] = __fmaf_rn(qv[r], mv[cc], a[r][cc]);
    }
    __syncthreads();

    float* sSim = sM;
    #pragma unroll
    for (int r = 0; r < 4; r++)
        #pragma unroll
        for (int cc = 0; cc < 4; cc++)
            sSim[(tok0 + r)*64 + c0 + cc] = a[r][cc];
    __syncthreads();

    if (tid < 64) {
        float best = -1e30f; int bi = 0;
        #pragma unroll 8
        for (int c = 0; c < C; c++) {
            float s = sSim[tid*64 + c];
            if (s > best) { best = s; bi = c; }   // strict > : first index on ties
        }
        g_bucketsB[(size_t)bh*T + chunk*64 + tid] = (unsigned char)bi;
    }
}

// ---------------- K3: cluster sums — byte buckets, vcmpeq4 scan (t-ascending chains) ----------------
__global__ __launch_bounds__(1024, 1) void k_sumsC() {
    __shared__ unsigned int sb[T/4];      // 8 KB
    int bh = blockIdx.x >> 1;
    int half = blockIdx.x & 1;
    int tid = threadIdx.x;
    int lane = tid & 31, wid = tid >> 5;
    size_t base = (size_t)bh * T;
    for (int i = tid; i < T/16; i += 1024)
        ((uint4*)sb)[i] = ((const uint4*)(g_bucketsB + base))[i];
    __syncthreads();

    int c = half*32 + wid;
    unsigned int cc = (unsigned int)c * 0x01010101u;
    float ax = 0.f, ay = 0.f;
    int cnt = 0;

    #define ADDTOK(tt) { float2 xv = ((const float2*)(g_knorm + (base + (tt))*D))[lane]; \
                         ax = __fadd_rn(ax, xv.x); ay = __fadd_rn(ay, xv.y); cnt++; }
    #define SCANW(u, t0) { unsigned int m = __vcmpeq4((u), cc); \
        if (m) { if (m & 0x000000FFu) ADDTOK((t0)+0); if (m & 0x0000FF00u) ADDTOK((t0)+1); \
                 if (m & 0x00FF0000u) ADDTOK((t0)+2); if (m & 0xFF000000u) ADDTOK((t0)+3); } }

    for (int t = 0; t < T; t += 16) {
        uint4 w = *(const uint4*)&sb[t >> 2];
        SCANW(w.x, t+0);
        SCANW(w.y, t+4);
        SCANW(w.z, t+8);
        SCANW(w.w, t+12);
    }
    #undef SCANW
    #undef ADDTOK

    float2 o; o.x = ax; o.y = ay;
    ((float2*)(g_part + ((size_t)bh*C + c) * D))[lane] = o;
    if (lane == 0) atomicAdd(&g_bins[(bh & (H-1))*C + c], cnt);
}

// ---------------- K4: means_upd (b-ascending combine + fused ssq + Markstein div) ----------------
__global__ void k_meansupd(const float* __restrict__ means) {
    int inst = blockIdx.x * blockDim.x + threadIdx.x;
    if (inst >= H*C) return;
    float sv[64];
    #pragma unroll 4
    for (int d = 0; d < D; d++) {
        float s = g_part[((size_t)0*1024 + inst)*D + d];
        s = __fadd_rn(s, g_part[((size_t)1*1024 + inst)*D + d]);
        s = __fadd_rn(s, g_part[((size_t)2*1024 + inst)*D + d]);
        s = __fadd_rn(s, g_part[((size_t)3*1024 + inst)*D + d]);
        sv[d] = s;
    }
    float ssq = 0.f;
    #pragma unroll
    for (int d = 0; d < D; d++) ssq = __fmaf_rn(sv[d], sv[d], ssq);
    float n = fmaxf(__fsqrt_rn(ssq), 1e-12f);
    float r = __frcp_rn(n);
    bool empty = (g_bins[inst] == 0);
    #pragma unroll 4
    for (int d = 0; d < D; d++) {
        float o = empty ? means[(size_t)inst*D + d] : fdiv_rn_m(sv[d], n, r);
        g_meansu[(size_t)inst*D + d] = o;
    }
}

// ---------------- K5: dists (b,h,c,t) = k_norm . means_upd^T ----------------
__global__ void k_dists() {
    __shared__ float sM[64*68];
    __shared__ float sT[64*68];
    int blk = blockIdx.x;
    int bh = blk / (T/64);
    int chunk = blk % (T/64);
    int h = bh % H;
    int tid = threadIdx.x;

    for (int i = tid; i < C*D; i += 256) {
        int c = i >> 6, d = i & 63;
        sM[d*68 + c] = g_meansu[(size_t)h*C*D + i];
    }
    size_t base = ((size_t)bh*T + (size_t)chunk*64) * D;
    for (int i = tid; i < 64*D; i += 256) {
        int r = i >> 6, d = i & 63;
        sT[d*68 + r] = g_knorm[base + i];
    }
    __syncthreads();

    int tx = tid & 15, ty = tid >> 4;
    int tok0 = ty*4, c0 = tx*4;
    float a[4][4];
    #pragma unroll
    for (int r = 0; r < 4; r++)
        #pragma unroll
        for (int cc = 0; cc < 4; cc++) a[r][cc] = 0.f;

    #pragma unroll 8
    for (int d = 0; d < 64; d++) {
        float4 q4 = *(const float4*)&sT[d*68 + tok0];
        float4 m4 = *(const float4*)&sM[d*68 + c0];
        float qv[4] = {q4.x, q4.y, q4.z, q4.w};
        float mv[4] = {m4.x, m4.y, m4.z, m4.w};
        #pragma unroll
        for (int r = 0; r < 4; r++)
            #pragma unroll
            for (int cc = 0; cc < 4; cc++)
                a[r][cc] = __fmaf_rn(qv[r], mv[cc], a[r][cc]);
    }
    __syncthreads();

    float* sSim = sM;    // alias: [c][tok] for coalesced store
    #pragma unroll
    for (int r = 0; r < 4; r++)
        #pragma unroll
        for (int cc = 0; cc < 4; cc++)
            sSim[(c0 + cc)*64 + tok0 + r] = a[r][cc];
    __syncthreads();

    for (int i = tid; i < C*64; i += 256) {
        int c = i >> 6, t = i & 63;
        g_dists[((size_t)bh*C + c)*T + (size_t)chunk*64 + t] = sSim[i];
    }
}

// ---------------- K6: top-128 per (b,h,c): radix select (reg keys, parallel scans) ----------------
__global__ void k_topk() {
    __shared__ int hist[256];
    __shared__ int SS[257];               // suffix sums (SS[256]=0)
    __shared__ unsigned int sh_pref;
    __shared__ int sh_k;
    __shared__ int outbuf[W];
    __shared__ int gtc;
    __shared__ unsigned int wmask[8*32];  // [wid][ch] equal-ballot masks
    __shared__ int prefCh[32];            // exclusive prefix of per-chunk totals

    int inst = blockIdx.x;
    int bh = inst / C;
    int c = inst % C;
    int tid = threadIdx.x, lane = tid & 31, wid = tid >> 5;

    // keys in registers: element i = 256*k + tid
    const float* row = g_dists + (size_t)inst * T;
    unsigned int key[32];
    #pragma unroll
    for (int k = 0; k < 32; k++) {
        unsigned int u = __float_as_uint(row[256*k + tid]);
        key[k] = (u & 0x80000000u) ? ~u : (u | 0x80000000u);  // monotone float->uint
    }

    unsigned int prefix = 0; int k = 128;
    for (int sh = 24; sh >= 0; sh -= 8) {
        hist[tid] = 0;
        __syncthreads();
        unsigned int hmask = (sh == 24) ? 0u : (0xFFFFFFFFu << (sh + 8));
        #pragma unroll
        for (int q = 0; q < 32; q++) {
            unsigned int kk = key[q];
            if ((kk & hmask) == prefix) atomicAdd(&hist[(kk >> sh) & 255], 1);
        }
        __syncthreads();
        // parallel inclusive suffix sum: SS[b] = sum_{b'>=b} hist[b']
        SS[tid] = hist[tid];
        if (tid == 0) SS[256] = 0;
        __syncthreads();
        #pragma unroll
        for (int off = 1; off < 256; off <<= 1) {
            int add = (tid + off < 256) ? SS[tid + off] : 0;
            __syncthreads();
            SS[tid] += add;
            __syncthreads();
        }
        // unique boundary bucket: SS[b] >= k && SS[b+1] < k
        if (SS[tid] >= k && SS[tid + 1] < k) {
            sh_pref = prefix | ((unsigned int)tid << sh);
            sh_k = k - SS[tid + 1];
        }
        __syncthreads();
        prefix = sh_pref; k = sh_k;
        __syncthreads();
    }
    unsigned int Tkey = prefix;
    int k_rem = k;
    int count_gt = 128 - k_rem;

    if (tid == 0) gtc = 0;
    __syncthreads();

    // strictly-greater (order irrelevant; indices sorted later)
    #pragma unroll
    for (int q = 0; q < 32; q++) {
        if (key[q] > Tkey) {
            int p = atomicAdd(&gtc, 1);
            outbuf[p] = 256*q + tid;
        }
    }

    // equal: ballot-matrix global rank (order = ascending index i = 256*ch + tid)
    unsigned int eqm = 0;
    #pragma unroll
    for (int ch = 0; ch < 32; ch++)
        if (key[ch] == Tkey) eqm |= (1u << ch);
    #pragma unroll
    for (int ch = 0; ch < 32; ch++) {
        unsigned int bal = __ballot_sync(0xffffffffu, (eqm >> ch) & 1u);
        if (lane == ch) wmask[wid*32 + ch] = bal;
    }
    __syncthreads();
    if (tid < 32) {  // warp 0: per-chunk totals + exclusive shfl-scan
        int tot = 0;
        #pragma unroll
        for (int w = 0; w < 8; w++) tot += __popc(wmask[w*32 + tid]);
        int t2 = tot;
        #pragma unroll
        for (int off = 1; off < 32; off <<= 1) {
            int vv = __shfl_up_sync(0xffffffffu, t2, off);
            if (lane >= off) t2 += vv;
        }
        prefCh[tid] = t2 - tot;   // exclusive prefix
    }
    __syncthreads();
    unsigned int ltmask = (1u << lane) - 1u;
    #pragma unroll
    for (int ch = 0; ch < 32; ch++) {
        if ((eqm >> ch) & 1u) {
            int base = prefCh[ch];
            for (int w = 0; w < wid; w++) base += __popc(wmask[w*32 + ch]);
            int rank = base + __popc(wmask[wid*32 + ch] & ltmask);
            if (rank < k_rem) outbuf[count_gt + rank] = 256*ch + tid;
        }
    }
    __syncthreads();

    // bitonic sort 128 ints ascending
    for (int size = 2; size <= 128; size <<= 1) {
        for (int stride = size >> 1; stride > 0; stride >>= 1) {
            __syncthreads();
            if (tid < 128) {
                int partner = tid ^ stride;
                if (partner > tid) {
                    bool up = ((tid & size) == 0);
                    int a = outbuf[tid], b2 = outbuf[partner];
                    if ((a > b2) == up) { outbuf[tid] = b2; outbuf[partner] = a; }
                }
            }
        }
    }
    __syncthreads();
    if (tid < 128) g_indices[(size_t)bh*T + c*W + tid] = outbuf[tid];
}

// ---------------- K7: windowed attention — fused dots+rel d-loop, no sK tile, 2 blocks/SM ----------------
#define ATTN_SMEM ((128*66 + 128*64 + 128*66) * 4 + 128*4 + 128*4)

__global__ __launch_bounds__(256, 2)
void k_attn(const float* __restrict__ qk, const float* __restrict__ v,
            const float* __restrict__ rw, float* __restrict__ out) {
    extern __shared__ float sm[];
    float* sQ = sm;                      // [128][66]
    float* sV = sQ + 128*66;             // [128][64]
    float* sR = sV + 128*64;             // [128][66]
    float* sN = sR + 128*66;             // [128] 1/||Q_j||
    int*   sIdx = (int*)(sN + 128);

    int inst = blockIdx.x;
    int bh = inst / NC;
    int n  = inst % NC;
    int h  = bh % H;
    int tid = threadIdx.x, lane = tid & 31, wid = tid >> 5;

    if (tid < 128) sIdx[tid] = g_indices[(size_t)bh*T + n*W + tid];
    __syncthreads();

    for (int r = wid; r < 128; r += 8) {
        int g = sIdx[r];
        size_t off = ((size_t)bh*T + g) * D;
        float2 a = ((const float2*)(qk + off))[lane];
        float2 c2 = ((const float2*)(v + off))[lane];
        sQ[r*66 + 2*lane] = a.x;  sQ[r*66 + 2*lane + 1] = a.y;
        sV[r*64 + 2*lane] = c2.x; sV[r*64 + 2*lane + 1] = c2.y;
        float2 rr = ((const float2*)(rw + ((size_t)r*H + h)*D))[lane];
        sR[r*66 + 2*lane] = rr.x; sR[r*66 + 2*lane + 1] = rr.y;
        // per-row inverse norm (tolerant path)
        float ssq = a.x*a.x + a.y*a.y;
        #pragma unroll
        for (int o = 16; o; o >>= 1) ssq += __shfl_xor_sync(0xffffffffu, ssq, o);
        if (lane == 0) sN[r] = __frcp_rn(fmaxf(__fsqrt_rn(ssq), 1e-12f));
    }
    __syncthreads();

    const float scale = 0.125f;

    for (int p = 0; p < 4; p++) {
        int irow[4];
        #pragma unroll
        for (int q = 0; q < 4; q++) irow[q] = wid + 8*q + 32*p;

        float a[4][4], rca[4][4];
        #pragma unroll
        for (int q = 0; q < 4; q++)
            #pragma unroll
            for (int jj = 0; jj < 4; jj++) { a[q][jj] = 0.f; rca[q][jj] = 0.f; }

        // fused: dots(raw) = Q_i.Q_j  AND  rel = Q_i . rw[127+j-i] (reuses qv regs)
        #pragma unroll 2
        for (int d2 = 0; d2 < 32; d2++) {
            float2 qv[4];
            #pragma unroll
            for (int q = 0; q < 4; q++) qv[q] = *(const float2*)&sQ[irow[q]*66 + 2*d2];
            #pragma unroll
            for (int jj = 0; jj < 4; jj++) {
                float2 kv = *(const float2*)&sQ[(lane + 32*jj)*66 + 2*d2];
                #pragma unroll
                for (int q = 0; q < 4; q++)
                    a[q][jj] += qv[q].x*kv.x + qv[q].y*kv.y;
            }
            #pragma unroll
            for (int q = 0; q < 4; q++) {
                #pragma unroll
                for (int jj = 0; jj < 4; jj++) {
                    int j = lane + 32*jj;
                    if (j < irow[q]) {
                        float2 rr = *(const float2*)&sR[(127 + j - irow[q])*66 + 2*d2];
                        rca[q][jj] += qv[q].x*rr.x + qv[q].y*rr.y;
                    }
                }
            }
        }

        // combine: dots/||Q_j|| + rel
        float nv[4];
        #pragma unroll
        for (int jj = 0; jj < 4; jj++) nv[jj] = sN[lane + 32*jj];
        #pragma unroll
        for (int q = 0; q < 4; q++)
            #pragma unroll
            for (int jj = 0; jj < 4; jj++)
                a[q][jj] = a[q][jj]*nv[jj] + rca[q][jj];

        float pr[4][4];
        #pragma unroll
        for (int q = 0; q < 4; q++) {
            int i = irow[q];
            float m = -1e30f;
            #pragma unroll
            for (int jj = 0; jj < 4; jj++) {
                int j = lane + 32*jj;
                a[q][jj] = (j == i) ? -50000.0f : a[q][jj]*scale;
                m = fmaxf(m, a[q][jj]);
            }
            #pragma unroll
            for (int o = 16; o; o >>= 1) m = fmaxf(m, __shfl_xor_sync(0xffffffffu, m, o));
            float s = 0.f;
            #pragma unroll
            for (int jj = 0; jj < 4; jj++) { pr[q][jj] = __expf(a[q][jj] - m); s += pr[q][jj]; }
            #pragma unroll
            for (int o = 16; o; o >>= 1) s += __shfl_xor_sync(0xffffffffu, s, o);
            float inv = __frcp_rn(s);
            #pragma unroll
            for (int jj = 0; jj < 4; jj++) pr[q][jj] *= inv;
        }

        float ox[4], oy[4];
        #pragma unroll
        for (int q = 0; q < 4; q++) { ox[q] = 0.f; oy[q] = 0.f; }
        #pragma unroll
        for (int jj = 0; jj < 4; jj++) {
            for (int js = 0; js < 32; js++) {
                float2 vv = ((const float2*)(sV + (jj*32 + js)*64))[lane];
                #pragma unroll
                for (int q = 0; q < 4; q++) {
                    float w = __shfl_sync(0xffffffffu, pr[q][jj], js);
                    ox[q] += w * vv.x;
                    oy[q] += w * vv.y;
                }
            }
        }

        #pragma unroll
        for (int q = 0; q < 4; q++) {
            int g = sIdx[irow[q]];
            float* dst = out + ((size_t)bh*T + g)*D + 2*lane;
            asm volatile("red.global.add.v2.f32 [%0], {%1,%2};"
                         :: "l"(dst), "f"(ox[q]), "f"(oy[q]) : "memory");
            if (lane == 0) atomicAdd(&g_count[(size_t)bh*T + g], 1);
        }
    }
}

// ---------------- K8: finalize out /= (count + 1e-5), warp per token, Markstein ----------------
__global__ void k_final(float* __restrict__ out) {
    int tok = blockIdx.x * (blockDim.x >> 5) + (threadIdx.x >> 5);
    int lane = threadIdx.x & 31;
    if (tok >= B*H*T) return;
    float dnm = (float)g_count[tok] + 1e-5f;
    float r = __frcp_rn(dnm);
    float2* p = (float2*)(out + (size_t)tok * D);
    float2 val = p[lane];
    val.x = fdiv_rn_m(val.x, dnm, r);
    val.y = fdiv_rn_m(val.y, dnm, r);
    p[lane] = val;
}

// ---------------- launch ----------------
extern "C" void kernel_launch(void* const* d_in, const int* in_sizes, int n_in,
                              void* d_out, int out_size) {
    const float* qk    = (const float*)d_in[0];
    const float* v     = (const float*)d_in[1];
    const float* means = (const float*)d_in[2];
    const float* rw    = (const float*)d_in[3];
    float* out = (float*)d_out;

    cudaFuncSetAttribute(k_attn, cudaFuncAttributeMaxDynamicSharedMemorySize, ATTN_SMEM);

    k_zero<<<2048, 256>>>(out);
    k_norm<<<(B*H*T + 255)/256, 256>>>(qk);
    k_buckets<<<BH*(T/64), 256>>>(means);
    k_sumsC<<<BH*2, 1024>>>();
    k_meansupd<<<(H*C + 255)/256, 256>>>(means);
    k_dists<<<BH*(T/64), 256>>>();
    k_topk<<<BH*C, 256>>>();
    k_attn<<<BH*NC, 256, ATTN_SMEM>>>(qk, v, rw, out);
    k_final<<<(B*H*T)/8, 256>>>(out);
}

// round 17
// speedup vs baseline: 1.5107x; 1.0517x over previous
#include <cuda_runtime.h>
#include <math.h>

#define B 4
#define H 16
#define T 8192
#define D 64
#define C 64
#define W 128
#define NC 64
#define BH (B*H)

// ---------------- scratch ----------------
__device__ float g_knorm[(size_t)B*H*T*D];
__device__ float g_dists[(size_t)B*H*C*T];
__device__ unsigned char g_bucketsB[B*H*T];
__device__ float g_part[(size_t)B*H*C*D];
__device__ int   g_bins[H*C];
__device__ float g_meansu[H*C*D];
__device__ int   g_indices[B*H*T];
__device__ int   g_count[B*H*T];

// Correctly-rounded division via Markstein sequence (r = __frcp_rn(n)).
__device__ __forceinline__ float fdiv_rn_m(float x, float n, float r) {
    float q = __fmul_rn(x, r);
    float e = __fmaf_rn(-q, n, x);
    return __fmaf_rn(e, r, q);
}

// ---------------- K0: zero accumulators ----------------
__global__ void k_zero(float* __restrict__ out) {
    size_t i = (size_t)blockIdx.x * blockDim.x + threadIdx.x;
    size_t stride = (size_t)gridDim.x * blockDim.x;
    const size_t NOUT = (size_t)B*H*T*D;
    for (size_t p = i; p < NOUT; p += stride) out[p] = 0.f;
    for (size_t p = i; p < (size_t)B*H*T; p += stride) g_count[p] = 0;
    for (size_t p = i; p < (size_t)H*C; p += stride) g_bins[p] = 0;
}

// ---------------- K1: k_norm (bit-exact: sequential fused fma ssq; Markstein div) ----------------
__global__ void k_norm(const float* __restrict__ qk) {
    int tok = blockIdx.x * blockDim.x + threadIdx.x;
    if (tok >= B*H*T) return;
    const float4* src = (const float4*)(qk + (size_t)tok * D);
    float v[64];
    #pragma unroll
    for (int i = 0; i < 16; i++) {
        float4 q = src[i];
        v[4*i+0] = q.x; v[4*i+1] = q.y; v[4*i+2] = q.z; v[4*i+3] = q.w;
    }
    float s = 0.f;
    #pragma unroll
    for (int d = 0; d < 64; d++) s = __fmaf_rn(v[d], v[d], s);
    float n = fmaxf(__fsqrt_rn(s), 1e-12f);
    float r = __frcp_rn(n);
    float4* dst = (float4*)(g_knorm + (size_t)tok * D);
    #pragma unroll
    for (int i = 0; i < 16; i++) {
        float4 o;
        o.x = fdiv_rn_m(v[4*i+0], n, r);
        o.y = fdiv_rn_m(v[4*i+1], n, r);
        o.z = fdiv_rn_m(v[4*i+2], n, r);
        o.w = fdiv_rn_m(v[4*i+3], n, r);
        dst[i] = o;
    }
}

// ---------------- K2: buckets = argmax_c (k_norm . means) ----------------
__global__ void k_buckets(const float* __restrict__ means) {
    __shared__ float sM[64*68];   // [d][c]
    __shared__ float sT[64*68];   // [d][tok]
    int blk = blockIdx.x;
    int bh = blk / (T/64);
    int chunk = blk % (T/64);
    int h = bh % H;
    int tid = threadIdx.x;

    for (int i = tid; i < C*D; i += 256) {
        int c = i >> 6, d = i & 63;
        sM[d*68 + c] = means[(size_t)h*C*D + i];
    }
    size_t base = ((size_t)bh*T + (size_t)chunk*64) * D;
    for (int i = tid; i < 64*D; i += 256) {
        int r = i >> 6, d = i & 63;
        sT[d*68 + r] = g_knorm[base + i];
    }
    __syncthreads();

    int tx = tid & 15, ty = tid >> 4;
    int tok0 = ty*4, c0 = tx*4;
    float a[4][4];
    #pragma unroll
    for (int r = 0; r < 4; r++)
        #pragma unroll
        for (int cc = 0; cc < 4; cc++) a[r][cc] = 0.f;

    #pragma unroll 8
    for (int d = 0; d < 64; d++) {
        float4 q4 = *(const float4*)&sT[d*68 + tok0];
        float4 m4 = *(const float4*)&sM[d*68 + c0];
        float qv[4] = {q4.x, q4.y, q4.z, q4.w};
        float mv[4] = {m4.x, m4.y, m4.z, m4.w};
        #pragma unroll
        for (int r = 0; r < 4; r++)
            #pragma unroll
            for (int cc = 0; cc < 4; cc++)
                a[r][cc] = __fmaf_rn(qv[r], mv[cc], a[r][cc]);
    }
    __syncthreads();

    float* sSim = sM;
    #pragma unroll
    for (int r = 0; r < 4; r++)
        #pragma unroll
        for (int cc = 0; cc < 4; cc++)
            sSim[(tok0 + r)*64 + c0 + cc] = a[r][cc];
    __syncthreads();

    if (tid < 64) {
        float best = -1e30f; int bi = 0;
        #pragma unroll 8
        for (int c = 0; c < C; c++) {
            float s = sSim[tid*64 + c];
            if (s > best) { best = s; bi = c; }   // strict > : first index on ties
        }
        g_bucketsB[(size_t)bh*T + chunk*64 + tid] = (unsigned char)bi;
    }
}

// ---------------- K3: cluster sums — byte buckets, vcmpeq4 scan (t-ascending chains) ----------------
__global__ __launch_bounds__(1024, 1) void k_sumsC() {
    __shared__ unsigned int sb[T/4];      // 8 KB
    int bh = blockIdx.x >> 1;
    int half = blockIdx.x & 1;
    int tid = threadIdx.x;
    int lane = tid & 31, wid = tid >> 5;
    size_t base = (size_t)bh * T;
    for (int i = tid; i < T/16; i += 1024)
        ((uint4*)sb)[i] = ((const uint4*)(g_bucketsB + base))[i];
    __syncthreads();

    int c = half*32 + wid;
    unsigned int cc = (unsigned int)c * 0x01010101u;
    float ax = 0.f, ay = 0.f;
    int cnt = 0;

    #define ADDTOK(tt) { float2 xv = ((const float2*)(g_knorm + (base + (tt))*D))[lane]; \
                         ax = __fadd_rn(ax, xv.x); ay = __fadd_rn(ay, xv.y); cnt++; }
    #define SCANW(u, t0) { unsigned int m = __vcmpeq4((u), cc); \
        if (m) { if (m & 0x000000FFu) ADDTOK((t0)+0); if (m & 0x0000FF00u) ADDTOK((t0)+1); \
                 if (m & 0x00FF0000u) ADDTOK((t0)+2); if (m & 0xFF000000u) ADDTOK((t0)+3); } }

    for (int t = 0; t < T; t += 16) {
        uint4 w = *(const uint4*)&sb[t >> 2];
        SCANW(w.x, t+0);
        SCANW(w.y, t+4);
        SCANW(w.z, t+8);
        SCANW(w.w, t+12);
    }
    #undef SCANW
    #undef ADDTOK

    float2 o; o.x = ax; o.y = ay;
    ((float2*)(g_part + ((size_t)bh*C + c) * D))[lane] = o;
    if (lane == 0) atomicAdd(&g_bins[(bh & (H-1))*C + c], cnt);
}

// ---------------- K4: means_upd (b-ascending combine + fused ssq + Markstein div) ----------------
__global__ void k_meansupd(const float* __restrict__ means) {
    int inst = blockIdx.x * blockDim.x + threadIdx.x;
    if (inst >= H*C) return;
    float sv[64];
    #pragma unroll 4
    for (int d = 0; d < D; d++) {
        float s = g_part[((size_t)0*1024 + inst)*D + d];
        s = __fadd_rn(s, g_part[((size_t)1*1024 + inst)*D + d]);
        s = __fadd_rn(s, g_part[((size_t)2*1024 + inst)*D + d]);
        s = __fadd_rn(s, g_part[((size_t)3*1024 + inst)*D + d]);
        sv[d] = s;
    }
    float ssq = 0.f;
    #pragma unroll
    for (int d = 0; d < D; d++) ssq = __fmaf_rn(sv[d], sv[d], ssq);
    float n = fmaxf(__fsqrt_rn(ssq), 1e-12f);
    float r = __frcp_rn(n);
    bool empty = (g_bins[inst] == 0);
    #pragma unroll 4
    for (int d = 0; d < D; d++) {
        float o = empty ? means[(size_t)inst*D + d] : fdiv_rn_m(sv[d], n, r);
        g_meansu[(size_t)inst*D + d] = o;
    }
}

// ---------------- K5: dists (b,h,c,t) = k_norm . means_upd^T ----------------
__global__ void k_dists() {
    __shared__ float sM[64*68];
    __shared__ float sT[64*68];
    int blk = blockIdx.x;
    int bh = blk / (T/64);
    int chunk = blk % (T/64);
    int h = bh % H;
    int tid = threadIdx.x;

    for (int i = tid; i < C*D; i += 256) {
        int c = i >> 6, d = i & 63;
        sM[d*68 + c] = g_meansu[(size_t)h*C*D + i];
    }
    size_t base = ((size_t)bh*T + (size_t)chunk*64) * D;
    for (int i = tid; i < 64*D; i += 256) {
        int r = i >> 6, d = i & 63;
        sT[d*68 + r] = g_knorm[base + i];
    }
    __syncthreads();

    int tx = tid & 15, ty = tid >> 4;
    int tok0 = ty*4, c0 = tx*4;
    float a[4][4];
    #pragma unroll
    for (int r = 0; r < 4; r++)
        #pragma unroll
        for (int cc = 0; cc < 4; cc++) a[r][cc] = 0.f;

    #pragma unroll 8
    for (int d = 0; d < 64; d++) {
        float4 q4 = *(const float4*)&sT[d*68 + tok0];
        float4 m4 = *(const float4*)&sM[d*68 + c0];
        float qv[4] = {q4.x, q4.y, q4.z, q4.w};
        float mv[4] = {m4.x, m4.y, m4.z, m4.w};
        #pragma unroll
        for (int r = 0; r < 4; r++)
            #pragma unroll
            for (int cc = 0; cc < 4; cc++)
                a[r][cc] = __fmaf_rn(qv[r], mv[cc], a[r][cc]);
    }
    __syncthreads();

    float* sSim = sM;    // alias: [c][tok] for coalesced store
    #pragma unroll
    for (int r = 0; r < 4; r++)
        #pragma unroll
        for (int cc = 0; cc < 4; cc++)
            sSim[(c0 + cc)*64 + tok0 + r] = a[r][cc];
    __syncthreads();

    for (int i = tid; i < C*64; i += 256) {
        int c = i >> 6, t = i & 63;
        g_dists[((size_t)bh*C + c)*T + (size_t)chunk*64 + t] = sSim[i];
    }
}

// ---------------- K6: top-128 per (b,h,c): radix select (reg keys, parallel scans) ----------------
__global__ void k_topk() {
    __shared__ int hist[256];
    __shared__ int SS[257];               // suffix sums (SS[256]=0)
    __shared__ unsigned int sh_pref;
    __shared__ int sh_k;
    __shared__ int outbuf[W];
    __shared__ int gtc;
    __shared__ unsigned int wmask[8*32];  // [wid][ch] equal-ballot masks
    __shared__ int prefCh[32];            // exclusive prefix of per-chunk totals

    int inst = blockIdx.x;
    int bh = inst / C;
    int c = inst % C;
    int tid = threadIdx.x, lane = tid & 31, wid = tid >> 5;

    // keys in registers: element i = 256*k + tid
    const float* row = g_dists + (size_t)inst * T;
    unsigned int key[32];
    #pragma unroll
    for (int k = 0; k < 32; k++) {
        unsigned int u = __float_as_uint(row[256*k + tid]);
        key[k] = (u & 0x80000000u) ? ~u : (u | 0x80000000u);  // monotone float->uint
    }

    unsigned int prefix = 0; int k = 128;
    for (int sh = 24; sh >= 0; sh -= 8) {
        hist[tid] = 0;
        __syncthreads();
        unsigned int hmask = (sh == 24) ? 0u : (0xFFFFFFFFu << (sh + 8));
        #pragma unroll
        for (int q = 0; q < 32; q++) {
            unsigned int kk = key[q];
            if ((kk & hmask) == prefix) atomicAdd(&hist[(kk >> sh) & 255], 1);
        }
        __syncthreads();
        // parallel inclusive suffix sum: SS[b] = sum_{b'>=b} hist[b']
        SS[tid] = hist[tid];
        if (tid == 0) SS[256] = 0;
        __syncthreads();
        #pragma unroll
        for (int off = 1; off < 256; off <<= 1) {
            int add = (tid + off < 256) ? SS[tid + off] : 0;
            __syncthreads();
            SS[tid] += add;
            __syncthreads();
        }
        // unique boundary bucket: SS[b] >= k && SS[b+1] < k
        if (SS[tid] >= k && SS[tid + 1] < k) {
            sh_pref = prefix | ((unsigned int)tid << sh);
            sh_k = k - SS[tid + 1];
        }
        __syncthreads();
        prefix = sh_pref; k = sh_k;
        __syncthreads();
    }
    unsigned int Tkey = prefix;
    int k_rem = k;
    int count_gt = 128 - k_rem;

    if (tid == 0) gtc = 0;
    __syncthreads();

    // strictly-greater (order irrelevant; indices sorted later)
    #pragma unroll
    for (int q = 0; q < 32; q++) {
        if (key[q] > Tkey) {
            int p = atomicAdd(&gtc, 1);
            outbuf[p] = 256*q + tid;
        }
    }

    // equal: ballot-matrix global rank (order = ascending index i = 256*ch + tid)
    unsigned int eqm = 0;
    #pragma unroll
    for (int ch = 0; ch < 32; ch++)
        if (key[ch] == Tkey) eqm |= (1u << ch);
    #pragma unroll
    for (int ch = 0; ch < 32; ch++) {
        unsigned int bal = __ballot_sync(0xffffffffu, (eqm >> ch) & 1u);
        if (lane == ch) wmask[wid*32 + ch] = bal;
    }
    __syncthreads();
    if (tid < 32) {  // warp 0: per-chunk totals + exclusive shfl-scan
        int tot = 0;
        #pragma unroll
        for (int w = 0; w < 8; w++) tot += __popc(wmask[w*32 + tid]);
        int t2 = tot;
        #pragma unroll
        for (int off = 1; off < 32; off <<= 1) {
            int vv = __shfl_up_sync(0xffffffffu, t2, off);
            if (lane >= off) t2 += vv;
        }
        prefCh[tid] = t2 - tot;   // exclusive prefix
    }
    __syncthreads();
    unsigned int ltmask = (1u << lane) - 1u;
    #pragma unroll
    for (int ch = 0; ch < 32; ch++) {
        if ((eqm >> ch) & 1u) {
            int base = prefCh[ch];
            for (int w = 0; w < wid; w++) base += __popc(wmask[w*32 + ch]);
            int rank = base + __popc(wmask[wid*32 + ch] & ltmask);
            if (rank < k_rem) outbuf[count_gt + rank] = 256*ch + tid;
        }
    }
    __syncthreads();

    // bitonic sort 128 ints ascending
    for (int size = 2; size <= 128; size <<= 1) {
        for (int stride = size >> 1; stride > 0; stride >>= 1) {
            __syncthreads();
            if (tid < 128) {
                int partner = tid ^ stride;
                if (partner > tid) {
                    bool up = ((tid & size) == 0);
                    int a = outbuf[tid], b2 = outbuf[partner];
                    if ((a > b2) == up) { outbuf[tid] = b2; outbuf[partner] = a; }
                }
            }
        }
    }
    __syncthreads();
    if (tid < 128) g_indices[(size_t)bh*T + c*W + tid] = outbuf[tid];
}

// ---------------- K7: windowed attention — float4 everywhere, paired-column AV ----------------
// smem: sQ[128][68], sV[128][64], sR[128][68], sN[128], sIdx[128] ≈ 101 KB → 2 blocks/SM
#define QP 68
#define ATTN_SMEM ((128*QP + 128*64 + 128*QP) * 4 + 128*4 + 128*4)

__global__ __launch_bounds__(256, 2)
void k_attn(const float* __restrict__ qk, const float* __restrict__ v,
            const float* __restrict__ rw, float* __restrict__ out) {
    extern __shared__ float sm[];
    float* sQ = sm;                      // [128][QP]
    float* sV = sQ + 128*QP;             // [128][64]
    float* sR = sV + 128*64;             // [128][QP]
    float* sN = sR + 128*QP;             // [128] 1/||Q_j||
    int*   sIdx = (int*)(sN + 128);

    int inst = blockIdx.x;
    int bh = inst / NC;
    int n  = inst % NC;
    int h  = bh % H;
    int tid = threadIdx.x, lane = tid & 31, wid = tid >> 5;

    if (tid < 128) sIdx[tid] = g_indices[(size_t)bh*T + n*W + tid];
    __syncthreads();

    for (int r = wid; r < 128; r += 8) {
        int g = sIdx[r];
        size_t off = ((size_t)bh*T + g) * D;
        float2 a = ((const float2*)(qk + off))[lane];
        float2 c2 = ((const float2*)(v + off))[lane];
        sQ[r*QP + 2*lane] = a.x;  sQ[r*QP + 2*lane + 1] = a.y;
        sV[r*64 + 2*lane] = c2.x; sV[r*64 + 2*lane + 1] = c2.y;
        float2 rr = ((const float2*)(rw + ((size_t)r*H + h)*D))[lane];
        sR[r*QP + 2*lane] = rr.x; sR[r*QP + 2*lane + 1] = rr.y;
        // per-row inverse norm (tolerant path)
        float ssq = a.x*a.x + a.y*a.y;
        #pragma unroll
        for (int o = 16; o; o >>= 1) ssq += __shfl_xor_sync(0xffffffffu, ssq, o);
        if (lane == 0) sN[r] = __frcp_rn(fmaxf(__fsqrt_rn(ssq), 1e-12f));
    }
    __syncthreads();

    const float scale = 0.125f;
    int halfsel = lane >> 4;       // AV: 0 = even columns, 1 = odd columns
    int dl = lane & 15;            // AV: float4 dim group

    for (int p = 0; p < 4; p++) {
        int irow[4];
        #pragma unroll
        for (int q = 0; q < 4; q++) irow[q] = wid + 8*q + 32*p;

        float a[4][4], rca[4][4];
        #pragma unroll
        for (int q = 0; q < 4; q++)
            #pragma unroll
            for (int jj = 0; jj < 4; jj++) { a[q][jj] = 0.f; rca[q][jj] = 0.f; }

        // fused float4 d-loop: dots(raw) = Q_i.Q_j  AND  rel = Q_i . rw[127+j-i]
        #pragma unroll 2
        for (int d4 = 0; d4 < 16; d4++) {
            float4 qv[4];
            #pragma unroll
            for (int q = 0; q < 4; q++) qv[q] = *(const float4*)&sQ[irow[q]*QP + 4*d4];
            #pragma unroll
            for (int jj = 0; jj < 4; jj++) {
                float4 kv = *(const float4*)&sQ[(lane + 32*jj)*QP + 4*d4];
                #pragma unroll
                for (int q = 0; q < 4; q++)
                    a[q][jj] += qv[q].x*kv.x + qv[q].y*kv.y + qv[q].z*kv.z + qv[q].w*kv.w;
            }
            #pragma unroll
            for (int q = 0; q < 4; q++) {
                #pragma unroll
                for (int jj = 0; jj < 4; jj++) {
                    int j = lane + 32*jj;
                    if (j < irow[q]) {
                        float4 rr = *(const float4*)&sR[(127 + j - irow[q])*QP + 4*d4];
                        rca[q][jj] += qv[q].x*rr.x + qv[q].y*rr.y + qv[q].z*rr.z + qv[q].w*rr.w;
                    }
                }
            }
        }

        // combine: dots/||Q_j|| + rel
        float nv[4];
        #pragma unroll
        for (int jj = 0; jj < 4; jj++) nv[jj] = sN[lane + 32*jj];
        #pragma unroll
        for (int q = 0; q < 4; q++)
            #pragma unroll
            for (int jj = 0; jj < 4; jj++)
                a[q][jj] = a[q][jj]*nv[jj] + rca[q][jj];

        float pr[4][4];
        #pragma unroll
        for (int q = 0; q < 4; q++) {
            int i = irow[q];
            float m = -1e30f;
            #pragma unroll
            for (int jj = 0; jj < 4; jj++) {
                int j = lane + 32*jj;
                a[q][jj] = (j == i) ? -50000.0f : a[q][jj]*scale;
                m = fmaxf(m, a[q][jj]);
            }
            #pragma unroll
            for (int o = 16; o; o >>= 1) m = fmaxf(m, __shfl_xor_sync(0xffffffffu, m, o));
            float s = 0.f;
            #pragma unroll
            for (int jj = 0; jj < 4; jj++) { pr[q][jj] = __expf(a[q][jj] - m); s += pr[q][jj]; }
            #pragma unroll
            for (int o = 16; o; o >>= 1) s += __shfl_xor_sync(0xffffffffu, s, o);
            float inv = __frcp_rn(s);
            #pragma unroll
            for (int jj = 0; jj < 4; jj++) pr[q][jj] *= inv;
        }

        // AV: paired columns. Lanes 0-15 accumulate even columns (dims 4dl..4dl+3),
        // lanes 16-31 odd columns; combine via shfl_xor(16); scatter red.v4 by lanes 0-15.
        float4 oa[4];
        #pragma unroll
        for (int q = 0; q < 4; q++) oa[q] = make_float4(0.f, 0.f, 0.f, 0.f);
        #pragma unroll
        for (int jj = 0; jj < 4; jj++) {
            #pragma unroll 4
            for (int s = 0; s < 16; s++) {
                int j = jj*32 + 2*s + halfsel;           // this lane's column
                float4 vv = *(const float4*)&sV[j*64 + 4*dl];
                #pragma unroll
                for (int q = 0; q < 4; q++) {
                    float w = __shfl_sync(0xffffffffu, pr[q][jj], 2*s + halfsel);
                    oa[q].x += w * vv.x;
                    oa[q].y += w * vv.y;
                    oa[q].z += w * vv.z;
                    oa[q].w += w * vv.w;
                }
            }
        }
        // combine even/odd halves
        #pragma unroll
        for (int q = 0; q < 4; q++) {
            oa[q].x += __shfl_xor_sync(0xffffffffu, oa[q].x, 16);
            oa[q].y += __shfl_xor_sync(0xffffffffu, oa[q].y, 16);
            oa[q].z += __shfl_xor_sync(0xffffffffu, oa[q].z, 16);
            oa[q].w += __shfl_xor_sync(0xffffffffu, oa[q].w, 16);
        }

        #pragma unroll
        for (int q = 0; q < 4; q++) {
            int g = sIdx[irow[q]];
            if (lane < 16) {
                float* dst = out + ((size_t)bh*T + g)*D + 4*dl;
                asm volatile("red.global.add.v4.f32 [%0], {%1,%2,%3,%4};"
                             :: "l"(dst), "f"(oa[q].x), "f"(oa[q].y),
                                "f"(oa[q].z), "f"(oa[q].w) : "memory");
            }
            if (lane == 0) atomicAdd(&g_count[(size_t)bh*T + g], 1);
        }
    }
}

// ---------------- K8: finalize out /= (count + 1e-5), warp per token, Markstein ----------------
__global__ void k_final(float* __restrict__ out) {
    int tok = blockIdx.x * (blockDim.x >> 5) + (threadIdx.x >> 5);
    int lane = threadIdx.x & 31;
    if (tok >= B*H*T) return;
    float dnm = (float)g_count[tok] + 1e-5f;
    float r = __frcp_rn(dnm);
    float2* p = (float2*)(out + (size_t)tok * D);
    float2 val = p[lane];
    val.x = fdiv_rn_m(val.x, dnm, r);
    val.y = fdiv_rn_m(val.y, dnm, r);
    p[lane] = val;
}

// ---------------- launch ----------------
extern "C" void kernel_launch(void* const* d_in, const int* in_sizes, int n_in,
                              void* d_out, int out_size) {
    const float* qk    = (const float*)d_in[0];
    const float* v     = (const float*)d_in[1];
    const float* means = (const float*)d_in[2];
    const float* rw    = (const float*)d_in[3];
    float* out = (float*)d_out;

    cudaFuncSetAttribute(k_attn, cudaFuncAttributeMaxDynamicSharedMemorySize, ATTN_SMEM);

    k_zero<<<2048, 256>>>(out);
    k_norm<<<(B*H*T + 255)/256, 256>>>(qk);
    k_buckets<<<BH*(T/64), 256>>>(means);
    k_sumsC<<<BH*2, 1024>>>();
    k_meansupd<<<(H*C + 255)/256, 256>>>(means);
    k_dists<<<BH*(T/64), 256>>>();
    k_topk<<<BH*C, 256>>>();
    k_attn<<<BH*NC, 256, ATTN_SMEM>>>(qk, v, rw, out);
    k_final<<<(B*H*T)/8, 256>>>(out);
}